// round 6
// baseline (speedup 1.0000x reference)
#include <cuda_runtime.h>
#include <cuda_bf16.h>
#include <cstdint>
#include <cstddef>

// ---------------------------------------------------------------------------
// Problem constants
// ---------------------------------------------------------------------------
#define BB      8
#define LL      1024
#define DM      512
#define DI      1024
#define NSTATE  16
#define RK      32
#define NT      (BB*LL)          // 8192 tokens
#define DEPTH   4

// ---------------------------------------------------------------------------
// Scratch buffers
// ---------------------------------------------------------------------------
__device__ float g_resid[NT*DM];
__device__ float g_h    [NT*DM];
__device__ float g_xz   [NT*2*DI];
__device__ float g_xc   [2*NT*DI];
__device__ float g_xdbl [2*NT*64];
__device__ float g_y    [2*NT*DI];
__device__ float g_o    [2*NT*DM];

// ---------------------------------------------------------------------------
// Helpers
// ---------------------------------------------------------------------------
__device__ __forceinline__ uint32_t smem_u32(const void* p){
    uint32_t a;
    asm("{ .reg .u64 t; cvta.to.shared.u64 t, %1; cvt.u32.u64 %0, t; }" : "=r"(a) : "l"(p));
    return a;
}
__device__ __forceinline__ float warpReduceSum(float v){
#pragma unroll
    for (int o=16;o>0;o>>=1) v += __shfl_xor_sync(0xffffffffu, v, o);
    return v;
}
__device__ __forceinline__ float silu_fast(float x){
    return x / (1.f + __expf(-x));
}

__device__ __forceinline__ void ldm_x4(uint32_t* r, uint32_t addr){
    asm volatile("ldmatrix.sync.aligned.m8n8.x4.shared.b16 {%0,%1,%2,%3}, [%4];"
        : "=r"(r[0]), "=r"(r[1]), "=r"(r[2]), "=r"(r[3]) : "r"(addr));
}
__device__ __forceinline__ void mma_bf16(float* c, const uint32_t* a, const uint32_t* b){
    asm volatile(
        "mma.sync.aligned.m16n8k16.row.col.f32.bf16.bf16.f32 "
        "{%0,%1,%2,%3}, {%4,%5,%6,%7}, {%8,%9}, {%0,%1,%2,%3};"
        : "+f"(c[0]), "+f"(c[1]), "+f"(c[2]), "+f"(c[3])
        : "r"(a[0]), "r"(a[1]), "r"(a[2]), "r"(a[3]), "r"(b[0]), "r"(b[1]));
}

// fp32x4 -> (hi,lo) bf16x4, stored into 80B-pitch smem rows
__device__ __forceinline__ void cvt_store80(char* hi_base, char* lo_base,
                                            int r, int q, float4 v){
    __nv_bfloat162 h0 = __floats2bfloat162_rn(v.x, v.y);
    __nv_bfloat162 h1 = __floats2bfloat162_rn(v.z, v.w);
    float2 f0 = __bfloat1622float2(h0);
    float2 f1 = __bfloat1622float2(h1);
    __nv_bfloat162 l0 = __floats2bfloat162_rn(v.x - f0.x, v.y - f0.y);
    __nv_bfloat162 l1 = __floats2bfloat162_rn(v.z - f1.x, v.w - f1.y);
    const int off = r*80 + q*8;
    uint2 hw, lw;
    hw.x = *reinterpret_cast<uint32_t*>(&h0); hw.y = *reinterpret_cast<uint32_t*>(&h1);
    lw.x = *reinterpret_cast<uint32_t*>(&l0); lw.y = *reinterpret_cast<uint32_t*>(&l1);
    *reinterpret_cast<uint2*>(hi_base + off) = hw;
    *reinterpret_cast<uint2*>(lo_base + off) = lw;
}

// ---------------------------------------------------------------------------
// LayerNorm + residual update (+ fused bidirectional add of prev out_proj)
// ---------------------------------------------------------------------------
__global__ void __launch_bounds__(128) ln_kernel(
    const float* __restrict__ src0, const float* __restrict__ o,
    float* __restrict__ resid,
    const float* __restrict__ w, const float* __restrict__ b,
    float* __restrict__ hout)
{
    __shared__ float sm[8];
    const int row = blockIdx.x, tid = threadIdx.x;
    float4 v = reinterpret_cast<const float4*>(src0 + (size_t)row*DM)[tid];
    if (o){
        const int t    = row & (LL-1);
        const int tokb = (row - t) + (LL-1 - t);
        float4 u1 = reinterpret_cast<const float4*>(o + (size_t)row*DM)[tid];
        float4 u2 = reinterpret_cast<const float4*>(o + (size_t)(NT + tokb)*DM)[tid];
        v.x += u1.x+u2.x; v.y += u1.y+u2.y; v.z += u1.z+u2.z; v.w += u1.w+u2.w;
    }
    reinterpret_cast<float4*>(resid + (size_t)row*DM)[tid] = v;

    float s = v.x+v.y+v.z+v.w;
    s = warpReduceSum(s);
    const int wid = tid>>5, lane = tid&31;
    if (lane==0) sm[wid]=s;
    __syncthreads();
    const float mu = (sm[0]+sm[1]+sm[2]+sm[3]) * (1.f/(float)DM);
    const float dx=v.x-mu, dy=v.y-mu, dz=v.z-mu, dw=v.w-mu;
    float q = dx*dx+dy*dy+dz*dz+dw*dw;
    q = warpReduceSum(q);
    if (lane==0) sm[4+wid]=q;
    __syncthreads();
    const float var = (sm[4]+sm[5]+sm[6]+sm[7]) * (1.f/(float)DM);
    const float rs = rsqrtf(var + 1e-5f);
    const float4 wv = reinterpret_cast<const float4*>(w)[tid];
    const float4 bv = reinterpret_cast<const float4*>(b)[tid];
    float4 ov;
    ov.x = dx*rs*wv.x + bv.x;
    ov.y = dy*rs*wv.y + bv.y;
    ov.z = dz*rs*wv.z + bv.z;
    ov.w = dw*rs*wv.w + bv.w;
    reinterpret_cast<float4*>(hout + (size_t)row*DM)[tid] = ov;
}

// ---------------------------------------------------------------------------
// Split-bf16 MMA GEMM, double-buffered, TERM-MAJOR MMA ordering
// (accumulator reuse distance 16 issues instead of 1).
// ---------------------------------------------------------------------------
template<int BM,int BN>
__global__ void __launch_bounds__(256) gemm_mma_kernel(
    const float* __restrict__ A, int lda,
    const float* __restrict__ W, int K,
    float* __restrict__ C, int ldc)
{
    constexpr int WGN = (BN==128) ? 4 : 2;
    constexpr int WGM = 8/WGN;
    constexpr int WM  = BM/WGM;
    constexpr int WN  = BN/WGN;
    constexpr int MT  = WM/16;
    constexpr int NTL = WN/8;
    constexpr int AHI = 0;
    constexpr int ALO = BM*80;
    constexpr int BHI = 2*BM*80;
    constexpr int BLO = BHI + BN*80;
    constexpr int STAGE = BHI + 2*BN*80;
    static_assert((BM*8)%256==0 && (BN*8)%256==0, "tile loads");

    extern __shared__ char smem[];
    const uint32_t sb = smem_u32(smem);

    const int tid  = threadIdx.x;
    const int wid  = tid>>5, lane = tid&31;
    const int m0   = blockIdx.y*BM, n0 = blockIdx.x*BN;
    const int wm0  = (wid/WGN)*WM;
    const int wn0  = (wid%WGN)*WN;

    float acc[MT][NTL][4];
#pragma unroll
    for (int i=0;i<MT;i++)
#pragma unroll
        for (int j=0;j<NTL;j++)
#pragma unroll
            for (int q=0;q<4;q++) acc[i][j][q]=0.f;

    const int a_row = (lane&7) + ((lane>>3)&1)*8;
    const int a_kb  = (lane>>4)*16;
    const int b_row = (lane&7) + (lane>>4)*8;
    const int b_kb  = ((lane>>3)&1)*16;

    float4 pa[BM/32];
    float4 pb[BN/32];
#pragma unroll
    for (int u=0;u<BM/32;u++){
        const int flat = tid + u*256;
        const int r = flat>>3, q = flat&7;
        pa[u] = *reinterpret_cast<const float4*>(A + (size_t)(m0+r)*lda + q*4);
    }
#pragma unroll
    for (int u=0;u<BN/32;u++){
        const int flat = tid + u*256;
        const int r = flat>>3, q = flat&7;
        pb[u] = *reinterpret_cast<const float4*>(W + (size_t)(n0+r)*K + q*4);
    }

    const int nchunk = K >> 5;
    for (int c=0; c<nchunk; ++c){
        char* st = smem + (c&1)*STAGE;
        const uint32_t sbs = sb + (uint32_t)((c&1)*STAGE);
#pragma unroll
        for (int u=0;u<BM/32;u++){
            const int flat = tid + u*256;
            const int r = flat>>3, q = flat&7;
            cvt_store80(st + AHI, st + ALO, r, q, pa[u]);
        }
#pragma unroll
        for (int u=0;u<BN/32;u++){
            const int flat = tid + u*256;
            const int r = flat>>3, q = flat&7;
            cvt_store80(st + BHI, st + BLO, r, q, pb[u]);
        }
        __syncthreads();
        if (c+1 < nchunk){
            const int k0 = (c+1)*32;
#pragma unroll
            for (int u=0;u<BM/32;u++){
                const int flat = tid + u*256;
                const int r = flat>>3, q = flat&7;
                pa[u] = *reinterpret_cast<const float4*>(A + (size_t)(m0+r)*lda + k0 + q*4);
            }
#pragma unroll
            for (int u=0;u<BN/32;u++){
                const int flat = tid + u*256;
                const int r = flat>>3, q = flat&7;
                pb[u] = *reinterpret_cast<const float4*>(W + (size_t)(n0+r)*K + k0 + q*4);
            }
        }
#pragma unroll
        for (int ks=0; ks<2; ++ks){
            uint32_t ah[MT][4], al[MT][4];
#pragma unroll
            for (int mt=0; mt<MT; ++mt){
                const uint32_t ra = (uint32_t)((wm0 + mt*16 + a_row)*80 + ks*32 + a_kb);
                ldm_x4(ah[mt], sbs + AHI + ra);
                ldm_x4(al[mt], sbs + ALO + ra);
            }
            uint32_t bh[NTL][2], bl[NTL][2];
#pragma unroll
            for (int tp=0; tp<NTL/2; ++tp){
                const uint32_t rb = (uint32_t)((wn0 + tp*16 + b_row)*80 + ks*32 + b_kb);
                uint32_t t4[4];
                ldm_x4(t4, sbs + BHI + rb);
                bh[tp*2][0]=t4[0]; bh[tp*2][1]=t4[1]; bh[tp*2+1][0]=t4[2]; bh[tp*2+1][1]=t4[3];
                ldm_x4(t4, sbs + BLO + rb);
                bl[tp*2][0]=t4[0]; bl[tp*2][1]=t4[1]; bl[tp*2+1][0]=t4[2]; bl[tp*2+1][1]=t4[3];
            }
            // term-major: all independent MMAs of one term before reusing accs
#pragma unroll
            for (int mt=0; mt<MT; ++mt)
#pragma unroll
                for (int nt=0; nt<NTL; ++nt)
                    mma_bf16(acc[mt][nt], ah[mt], bh[nt]);
#pragma unroll
            for (int mt=0; mt<MT; ++mt)
#pragma unroll
                for (int nt=0; nt<NTL; ++nt)
                    mma_bf16(acc[mt][nt], ah[mt], bl[nt]);
#pragma unroll
            for (int mt=0; mt<MT; ++mt)
#pragma unroll
                for (int nt=0; nt<NTL; ++nt)
                    mma_bf16(acc[mt][nt], al[mt], bh[nt]);
        }
    }

    const int cr = lane>>2;
    const int cc = (lane&3)*2;
#pragma unroll
    for (int mt=0; mt<MT; ++mt){
        const int rbase = m0 + wm0 + mt*16 + cr;
#pragma unroll
        for (int nt=0; nt<NTL; ++nt){
            const int col = n0 + wn0 + nt*8 + cc;
            float2 v0; v0.x = acc[mt][nt][0]; v0.y = acc[mt][nt][1];
            float2 v1; v1.x = acc[mt][nt][2]; v1.y = acc[mt][nt][3];
            *reinterpret_cast<float2*>(C + (size_t)rbase*ldc + col)     = v0;
            *reinterpret_cast<float2*>(C + (size_t)(rbase+8)*ldc + col) = v1;
        }
    }
}

// ---------------------------------------------------------------------------
// Depthwise causal conv (k=4) + bias + silu, both directions.
// ---------------------------------------------------------------------------
__global__ void __launch_bounds__(256) conv_kernel(
    const float* __restrict__ xz,
    const float* __restrict__ cw, const float* __restrict__ cb,
    float* __restrict__ xc)
{
    const int flat = blockIdx.x*256 + threadIdx.x;
    const int d   = flat & (DI-1);
    const int t   = (flat >> 10) & (LL-1);
    const int b   = (flat >> 20) & (BB-1);
    const int dir = flat >> 23;

    float acc = cb[d];
    const float w0=cw[d*4+0], w1=cw[d*4+1], w2=cw[d*4+2], w3=cw[d*4+3];
    const float* src = xz + ((size_t)b*LL)*(2*DI) + d;
#pragma unroll
    for (int j=0;j<4;j++){
        const int tt = t - 3 + j;
        if (tt >= 0){
            const int st = dir ? (LL-1-tt) : tt;
            const float wj = (j==0)?w0:(j==1)?w1:(j==2)?w2:w3;
            acc += wj * src[(size_t)st*(2*DI)];
        }
    }
    acc = silu_fast(acc);
    xc[(size_t)dir*NT*DI + ((size_t)(b*LL+t))*DI + d] = acc;
}

// ---------------------------------------------------------------------------
// Selective scan, 2 threads per channel (8 states each).
// Grid: 2 dir x 8 batch x 16 d-chunks(64ch) = 256 blocks, 128 threads.
// dt projection fused (each thread: 16-term half-dot, shfl combine).
// ---------------------------------------------------------------------------
#define TTILE 16
__global__ void __launch_bounds__(128) scan_kernel(
    const float* __restrict__ xc,   const float* __restrict__ xdbl,
    const float* __restrict__ xz,
    const float* __restrict__ A_log,const float* __restrict__ Dp,
    const float* __restrict__ dtw,  const float* __restrict__ dtb,
    float* __restrict__ yout)
{
    __shared__ float su [TTILE][64];
    __shared__ float sz [TTILE][64];
    __shared__ float sXD[TTILE][64];

    const int bx  = blockIdx.x;            // dir*128 + b*16 + dch
    const int dir = bx >> 7;
    const int b   = (bx >> 4) & 7;
    const int dch = bx & 15;
    const int tid = threadIdx.x;
    const int c    = tid >> 1;
    const int half = tid & 1;
    const int d    = dch*64 + c;
    const int noff = half*8;

    float a[8], h[8];
#pragma unroll
    for (int j=0;j<8;j++){
        a[j] = -expf(A_log[(size_t)d*NSTATE + noff + j]);
        h[j] = 0.f;
    }
    const float a0 = -expf(A_log[(size_t)d*NSTATE]);
    unsigned ok = 1u;
#pragma unroll
    for (int j=0;j<8;j++){
        const float expect = a0*(float)(noff+j+1);
        ok &= (fabsf(a[j] - expect) <= 1e-4f*fabsf(a[j])) ? 1u : 0u;
    }
    ok &= __shfl_xor_sync(0xffffffffu, ok, 1);
    const bool fast = (ok != 0u);
    const float Dv = Dp[d];

    float w[16];
#pragma unroll
    for (int r=0;r<16;r++) w[r] = dtw[(size_t)d*RK + half*16 + r];
    const float bias = dtb[d];

    const size_t cb = (size_t)dir*NT*DI + (size_t)b*LL*DI + (size_t)dch*64;
    const float* xcp = xc + cb;
    float*       yp  = yout + cb;
    const float* xdp = xdbl + ((size_t)dir*NT + (size_t)b*LL)*64;
    const float* zp  = xz + (size_t)b*LL*(2*DI) + DI + (size_t)dch*64;

    for (int t0=0; t0<LL; t0+=TTILE){
        __syncthreads();
#pragma unroll
        for (int k=0;k<8;k++){
            const int idx = tid + k*128;
            const int row = idx>>6, col = idx&63;
            const int t = t0 + row;
            su [row][col] = xcp[(size_t)t*DI + col];
            sXD[row][col] = xdp[(size_t)t*64 + col];
            const int zt = dir ? (LL-1-t) : t;
            sz [row][col] = zp[(size_t)zt*(2*DI) + col];
        }
        __syncthreads();

        // dt pre-pass: half-dot + pair combine
        float dtv[TTILE];
#pragma unroll
        for (int i=0;i<TTILE;i++){
            float s0=0.f,s1=0.f,s2=0.f,s3=0.f;
            const float* xr = &sXD[i][half*16];
#pragma unroll
            for (int r=0;r<16;r+=4){
                s0 += xr[r+0]*w[r+0];
                s1 += xr[r+1]*w[r+1];
                s2 += xr[r+2]*w[r+2];
                s3 += xr[r+3]*w[r+3];
            }
            float v = (s0+s1)+(s2+s3);
            v += __shfl_xor_sync(0xffffffffu, v, 1);
            v += bias;
            dtv[i] = (v > 20.f) ? v : __logf(1.f + __expf(v));
        }

        if (fast){
#pragma unroll
            for (int i=0;i<TTILE;i++){
                const float dt  = dtv[i];
                const float u   = su[i][c];
                const float dtu = dt * u;
                const float rr  = __expf(dt * a0);
                const float r2 = rr*rr, r4 = r2*r2;
                const float r3 = r2*rr, r5 = r4*rr, r6 = r4*r2, r7 = r4*r3, r8 = r4*r4;
                const float base = half ? r8 : 1.f;
                const float p[8] = {base*rr, base*r2, base*r3, base*r4,
                                    base*r5, base*r6, base*r7, base*r8};
                float y0=0.f, y1=0.f;
#pragma unroll
                for (int j=0;j<8;j++){
                    h[j] = p[j]*h[j] + dtu * sXD[i][32+noff+j];
                    const float cterm = h[j] * sXD[i][48+noff+j];
                    if (j&1) y1 += cterm; else y0 += cterm;
                }
                float ys = y0 + y1;
                ys += __shfl_xor_sync(0xffffffffu, ys, 1);
                if (half==0){
                    const float y = (u*Dv + ys) * silu_fast(sz[i][c]);
                    yp[(size_t)(t0+i)*DI + c] = y;
                }
            }
        } else {
#pragma unroll
            for (int i=0;i<TTILE;i++){
                const float dt  = dtv[i];
                const float u   = su[i][c];
                const float dtu = dt * u;
                float y0=0.f, y1=0.f;
#pragma unroll
                for (int j=0;j<8;j++){
                    const float dA = __expf(dt * a[j]);
                    h[j] = dA*h[j] + dtu * sXD[i][32+noff+j];
                    const float cterm = h[j] * sXD[i][48+noff+j];
                    if (j&1) y1 += cterm; else y0 += cterm;
                }
                float ys = y0 + y1;
                ys += __shfl_xor_sync(0xffffffffu, ys, 1);
                if (half==0){
                    const float y = (u*Dv + ys) * silu_fast(sz[i][c]);
                    yp[(size_t)(t0+i)*DI + c] = y;
                }
            }
        }
    }
}

// ---------------------------------------------------------------------------
// Final output: hidden[b,t,:] = o_fwd[b,t,:] + o_bwd[b,L-1-t,:]
// ---------------------------------------------------------------------------
__global__ void __launch_bounds__(256) add_kernel(
    const float* __restrict__ o, float* __restrict__ dst)
{
    const int flat = blockIdx.x*256 + threadIdx.x;
    const int e = flat & (DM-1);
    const int t = (flat >> 9) & (LL-1);
    const int b = flat >> 19;
    const int tok  = b*LL + t;
    const int tokb = b*LL + (LL-1-t);
    dst[flat] = o[(size_t)tok*DM + e] + o[(size_t)(NT + tokb)*DM + e];
}

// ---------------------------------------------------------------------------
// Launch
// ---------------------------------------------------------------------------
extern "C" void kernel_launch(void* const* d_in, const int* in_sizes, int n_in,
                              void* d_out, int out_size)
{
    (void)in_sizes; (void)n_in; (void)out_size;
    const float* x      = (const float*)d_in[0];
    const float* norm_w = (const float*)d_in[1];
    const float* norm_b = (const float*)d_in[2];
    const float* in_w   = (const float*)d_in[3];
    const float* conv_w = (const float*)d_in[4];
    const float* conv_b = (const float*)d_in[5];
    const float* xp_w   = (const float*)d_in[6];
    const float* dtp_w  = (const float*)d_in[7];
    const float* dtp_b  = (const float*)d_in[8];
    const float* A_log  = (const float*)d_in[9];
    const float* Dp     = (const float*)d_in[10];
    const float* out_w  = (const float*)d_in[11];
    float* dout = (float*)d_out;

    float *resid,*hbuf,*xz,*xc,*xdbl,*yb,*ob;
    cudaGetSymbolAddress((void**)&resid, g_resid);
    cudaGetSymbolAddress((void**)&hbuf,  g_h);
    cudaGetSymbolAddress((void**)&xz,    g_xz);
    cudaGetSymbolAddress((void**)&xc,    g_xc);
    cudaGetSymbolAddress((void**)&xdbl,  g_xdbl);
    cudaGetSymbolAddress((void**)&yb,    g_y);
    cudaGetSymbolAddress((void**)&ob,    g_o);

    constexpr int SMEM_BIG = 2*(2*128*80 + 2*128*80);   // 81920 (128x128)
    constexpr int SMEM_SML = 2*(2*64*80 + 2*64*80);     // 40960 (64x64)
    static bool attr_done = false;
    if (!attr_done){
        cudaFuncSetAttribute((const void*)gemm_mma_kernel<128,128>,
                             cudaFuncAttributeMaxDynamicSharedMemorySize, SMEM_BIG);
        cudaFuncSetAttribute((const void*)gemm_mma_kernel<64,64>,
                             cudaFuncAttributeMaxDynamicSharedMemorySize, SMEM_SML);
        attr_done = true;
    }

    for (int i=0;i<DEPTH;i++){
        ln_kernel<<<NT,128>>>( (i==0)? x : resid, (i==0)? (const float*)nullptr : ob,
                               resid, norm_w + i*DM, norm_b + i*DM, hbuf );

        // GEMM1: xz[8192,2048] = h @ in_w^T
        gemm_mma_kernel<128,128><<<dim3(2048/128, 8192/128), 256, SMEM_BIG>>>(
            hbuf, DM, in_w + (size_t)i*2*DI*DM, DM, xz, 2*DI);

        conv_kernel<<<(2*NT*DI)/256,256>>>(xz, conv_w + i*DI*4, conv_b + i*DI, xc);

        // GEMM2: xdbl[16384,64] = xc @ xp_w^T
        gemm_mma_kernel<64,64><<<dim3(1, 16384/64), 256, SMEM_SML>>>(
            xc, DI, xp_w + (size_t)i*64*DI, DI, xdbl, 64);

        // selective scan with fused dt-projection + gating
        scan_kernel<<<256,128>>>(xc, xdbl, xz,
                                 A_log + (size_t)i*DI*NSTATE, Dp + i*DI,
                                 dtp_w + (size_t)i*DI*RK, dtp_b + i*DI, yb);

        // GEMM4: o[16384,512] = y @ out_w^T
        gemm_mma_kernel<128,128><<<dim3(512/128, 16384/128), 256, SMEM_BIG>>>(
            yb, DI, out_w + (size_t)i*DM*DI, DI, ob, DM);
    }
    add_kernel<<<(NT*DM)/256,256>>>(ob, dout);
}

// round 7
// speedup vs baseline: 1.0551x; 1.0551x over previous
#include <cuda_runtime.h>
#include <cuda_bf16.h>
#include <cstdint>
#include <cstddef>

// ---------------------------------------------------------------------------
// Problem constants
// ---------------------------------------------------------------------------
#define BB      8
#define LL      1024
#define DM      512
#define DI      1024
#define NSTATE  16
#define RK      32
#define NT      (BB*LL)          // 8192 tokens
#define DEPTH   4

// ---------------------------------------------------------------------------
// Scratch buffers
// ---------------------------------------------------------------------------
__device__ float         g_resid[NT*DM];
__device__ __nv_bfloat16 g_h_hi [NT*DM];
__device__ __nv_bfloat16 g_h_lo [NT*DM];
__device__ float         g_xz   [NT*2*DI];
__device__ __nv_bfloat16 g_xc_hi[2*NT*DI];
__device__ __nv_bfloat16 g_xc_lo[2*NT*DI];
__device__ float         g_xdbl [2*NT*64];
__device__ __nv_bfloat16 g_y_hi [2*NT*DI];
__device__ __nv_bfloat16 g_y_lo [2*NT*DI];
__device__ float         g_o    [2*NT*DM];
// converted weights (hi/lo planes), all layers
__device__ __nv_bfloat16 g_w1_hi[DEPTH*2*DI*DM];
__device__ __nv_bfloat16 g_w1_lo[DEPTH*2*DI*DM];
__device__ __nv_bfloat16 g_w2_hi[DEPTH*64*DI];
__device__ __nv_bfloat16 g_w2_lo[DEPTH*64*DI];
__device__ __nv_bfloat16 g_w4_hi[DEPTH*DM*DI];
__device__ __nv_bfloat16 g_w4_lo[DEPTH*DM*DI];

// ---------------------------------------------------------------------------
// Helpers
// ---------------------------------------------------------------------------
__device__ __forceinline__ uint32_t smem_u32(const void* p){
    uint32_t a;
    asm("{ .reg .u64 t; cvta.to.shared.u64 t, %1; cvt.u32.u64 %0, t; }" : "=r"(a) : "l"(p));
    return a;
}
__device__ __forceinline__ float warpReduceSum(float v){
#pragma unroll
    for (int o=16;o>0;o>>=1) v += __shfl_xor_sync(0xffffffffu, v, o);
    return v;
}
__device__ __forceinline__ float silu_fast(float x){
    return x / (1.f + __expf(-x));
}
__device__ __forceinline__ void ldm_x4(uint32_t* r, uint32_t addr){
    asm volatile("ldmatrix.sync.aligned.m8n8.x4.shared.b16 {%0,%1,%2,%3}, [%4];"
        : "=r"(r[0]), "=r"(r[1]), "=r"(r[2]), "=r"(r[3]) : "r"(addr));
}
__device__ __forceinline__ void mma_bf16(float* c, const uint32_t* a, const uint32_t* b){
    asm volatile(
        "mma.sync.aligned.m16n8k16.row.col.f32.bf16.bf16.f32 "
        "{%0,%1,%2,%3}, {%4,%5,%6,%7}, {%8,%9}, {%0,%1,%2,%3};"
        : "+f"(c[0]), "+f"(c[1]), "+f"(c[2]), "+f"(c[3])
        : "r"(a[0]), "r"(a[1]), "r"(a[2]), "r"(a[3]), "r"(b[0]), "r"(b[1]));
}
__device__ __forceinline__ void cp_async16(uint32_t dst, const void* src){
    asm volatile("cp.async.cg.shared.global [%0], [%1], 16;" :: "r"(dst), "l"(src));
}
__device__ __forceinline__ void cp_commit(){
    asm volatile("cp.async.commit_group;");
}
template<int N>
__device__ __forceinline__ void cp_wait(){
    asm volatile("cp.async.wait_group %0;" :: "n"(N));
}
__device__ __forceinline__ void split_bf16(float v, __nv_bfloat16& hi, __nv_bfloat16& lo){
    hi = __float2bfloat16(v);
    lo = __float2bfloat16(v - __bfloat162float(hi));
}

// ---------------------------------------------------------------------------
// Weight conversion: fp32 -> hi/lo bf16 planes (float4 granularity)
// ---------------------------------------------------------------------------
__global__ void __launch_bounds__(256) wcvt_kernel(
    const float* __restrict__ src,
    __nv_bfloat16* __restrict__ hi, __nv_bfloat16* __restrict__ lo, int n4)
{
    const int i = blockIdx.x*256 + threadIdx.x;
    if (i >= n4) return;
    float4 v = reinterpret_cast<const float4*>(src)[i];
    __nv_bfloat162 h0 = __floats2bfloat162_rn(v.x, v.y);
    __nv_bfloat162 h1 = __floats2bfloat162_rn(v.z, v.w);
    float2 f0 = __bfloat1622float2(h0);
    float2 f1 = __bfloat1622float2(h1);
    __nv_bfloat162 l0 = __floats2bfloat162_rn(v.x - f0.x, v.y - f0.y);
    __nv_bfloat162 l1 = __floats2bfloat162_rn(v.z - f1.x, v.w - f1.y);
    uint2 hw, lw;
    hw.x = *reinterpret_cast<uint32_t*>(&h0); hw.y = *reinterpret_cast<uint32_t*>(&h1);
    lw.x = *reinterpret_cast<uint32_t*>(&l0); lw.y = *reinterpret_cast<uint32_t*>(&l1);
    reinterpret_cast<uint2*>(hi)[i] = hw;
    reinterpret_cast<uint2*>(lo)[i] = lw;
}

// ---------------------------------------------------------------------------
// LayerNorm + residual (+ fused bidirectional add); writes h as bf16 planes.
// ---------------------------------------------------------------------------
__global__ void __launch_bounds__(128) ln_kernel(
    const float* __restrict__ src0, const float* __restrict__ o,
    float* __restrict__ resid,
    const float* __restrict__ w, const float* __restrict__ b,
    __nv_bfloat16* __restrict__ h_hi, __nv_bfloat16* __restrict__ h_lo)
{
    __shared__ float sm[8];
    const int row = blockIdx.x, tid = threadIdx.x;
    float4 v = reinterpret_cast<const float4*>(src0 + (size_t)row*DM)[tid];
    if (o){
        const int t    = row & (LL-1);
        const int tokb = (row - t) + (LL-1 - t);
        float4 u1 = reinterpret_cast<const float4*>(o + (size_t)row*DM)[tid];
        float4 u2 = reinterpret_cast<const float4*>(o + (size_t)(NT + tokb)*DM)[tid];
        v.x += u1.x+u2.x; v.y += u1.y+u2.y; v.z += u1.z+u2.z; v.w += u1.w+u2.w;
    }
    reinterpret_cast<float4*>(resid + (size_t)row*DM)[tid] = v;

    float s = v.x+v.y+v.z+v.w;
    s = warpReduceSum(s);
    const int wid = tid>>5, lane = tid&31;
    if (lane==0) sm[wid]=s;
    __syncthreads();
    const float mu = (sm[0]+sm[1]+sm[2]+sm[3]) * (1.f/(float)DM);
    const float dx=v.x-mu, dy=v.y-mu, dz=v.z-mu, dw=v.w-mu;
    float q = dx*dx+dy*dy+dz*dz+dw*dw;
    q = warpReduceSum(q);
    if (lane==0) sm[4+wid]=q;
    __syncthreads();
    const float var = (sm[4]+sm[5]+sm[6]+sm[7]) * (1.f/(float)DM);
    const float rs = rsqrtf(var + 1e-5f);
    const float4 wv = reinterpret_cast<const float4*>(w)[tid];
    const float4 bv = reinterpret_cast<const float4*>(b)[tid];
    float4 ov;
    ov.x = dx*rs*wv.x + bv.x;
    ov.y = dy*rs*wv.y + bv.y;
    ov.z = dz*rs*wv.z + bv.z;
    ov.w = dw*rs*wv.w + bv.w;
    __nv_bfloat162 h0 = __floats2bfloat162_rn(ov.x, ov.y);
    __nv_bfloat162 h1 = __floats2bfloat162_rn(ov.z, ov.w);
    float2 f0 = __bfloat1622float2(h0);
    float2 f1 = __bfloat1622float2(h1);
    __nv_bfloat162 l0 = __floats2bfloat162_rn(ov.x - f0.x, ov.y - f0.y);
    __nv_bfloat162 l1 = __floats2bfloat162_rn(ov.z - f1.x, ov.w - f1.y);
    uint2 hw, lw;
    hw.x = *reinterpret_cast<uint32_t*>(&h0); hw.y = *reinterpret_cast<uint32_t*>(&h1);
    lw.x = *reinterpret_cast<uint32_t*>(&l0); lw.y = *reinterpret_cast<uint32_t*>(&l1);
    reinterpret_cast<uint2*>(h_hi + (size_t)row*DM)[tid] = hw;
    reinterpret_cast<uint2*>(h_lo + (size_t)row*DM)[tid] = lw;
}

// ---------------------------------------------------------------------------
// Split-bf16 MMA GEMM over precomputed hi/lo planes.
// cp.async 2-stage pipeline, no in-loop conversion, term-major MMA order.
// Row pitch 80B (16B-aligned, conflict-free ldmatrix).
// ---------------------------------------------------------------------------
template<int BM,int BN>
__global__ void __launch_bounds__(256) gemm_bf16_kernel(
    const __nv_bfloat16* __restrict__ Ahi, const __nv_bfloat16* __restrict__ Alo, int lda,
    const __nv_bfloat16* __restrict__ Whi, const __nv_bfloat16* __restrict__ Wlo, int K,
    float* __restrict__ C, int ldc)
{
    constexpr int WGN = (BN==128) ? 4 : 2;
    constexpr int WGM = 8/WGN;
    constexpr int WM  = BM/WGM;
    constexpr int WN  = BN/WGN;
    constexpr int MT  = WM/16;
    constexpr int NTL = WN/8;
    constexpr int AHI = 0;
    constexpr int ALO = BM*80;
    constexpr int BHI = 2*BM*80;
    constexpr int BLO = BHI + BN*80;
    constexpr int STAGE = BHI + 2*BN*80;
    static_assert(BM==128, "loader assumes BM=128");

    extern __shared__ __align__(16) char smem[];
    const uint32_t sb = smem_u32(smem);

    const int tid  = threadIdx.x;
    const int wid  = tid>>5, lane = tid&31;
    const int m0   = blockIdx.y*BM, n0 = blockIdx.x*BN;
    const int wm0  = (wid/WGN)*WM;
    const int wn0  = (wid%WGN)*WN;

    float acc[MT][NTL][4];
#pragma unroll
    for (int i=0;i<MT;i++)
#pragma unroll
        for (int j=0;j<NTL;j++)
#pragma unroll
            for (int q=0;q<4;q++) acc[i][j][q]=0.f;

    const int a_row = (lane&7) + ((lane>>3)&1)*8;
    const int a_kb  = (lane>>4)*16;
    const int b_row = (lane&7) + (lane>>4)*8;
    const int b_kb  = ((lane>>3)&1)*16;

    // stage loader: each 16B chunk = 8 bf16
    auto issue_stage = [&](int s, int k0){
        const uint32_t base = sb + (uint32_t)(s*STAGE);
#pragma unroll
        for (int u=0; u<BM/64; ++u){
            const int flat = tid + u*256;
            const int r = flat>>2, q = flat&3;
            const size_t go = (size_t)(m0+r)*lda + k0 + q*8;
            cp_async16(base + AHI + r*80 + q*16, Ahi + go);
            cp_async16(base + ALO + r*80 + q*16, Alo + go);
        }
#pragma unroll
        for (int u=0; u<BN/64; ++u){
            const int flat = tid + u*256;
            const int r = flat>>2, q = flat&3;
            const size_t go = (size_t)(n0+r)*K + k0 + q*8;
            cp_async16(base + BHI + r*80 + q*16, Whi + go);
            cp_async16(base + BLO + r*80 + q*16, Wlo + go);
        }
        cp_commit();
    };

    const int nchunk = K >> 5;
    issue_stage(0, 0);

    for (int c=0; c<nchunk; ++c){
        if (c+1 < nchunk){
            issue_stage((c+1)&1, (c+1)*32);
            cp_wait<1>();
        } else {
            cp_wait<0>();
        }
        __syncthreads();
        const uint32_t sbs = sb + (uint32_t)((c&1)*STAGE);
#pragma unroll
        for (int ks=0; ks<2; ++ks){
            uint32_t ah[MT][4], al[MT][4];
#pragma unroll
            for (int mt=0; mt<MT; ++mt){
                const uint32_t ra = (uint32_t)((wm0 + mt*16 + a_row)*80 + ks*32 + a_kb);
                ldm_x4(ah[mt], sbs + AHI + ra);
                ldm_x4(al[mt], sbs + ALO + ra);
            }
            uint32_t bh[NTL][2], bl[NTL][2];
#pragma unroll
            for (int tp=0; tp<NTL/2; ++tp){
                const uint32_t rb = (uint32_t)((wn0 + tp*16 + b_row)*80 + ks*32 + b_kb);
                uint32_t t4[4];
                ldm_x4(t4, sbs + BHI + rb);
                bh[tp*2][0]=t4[0]; bh[tp*2][1]=t4[1]; bh[tp*2+1][0]=t4[2]; bh[tp*2+1][1]=t4[3];
                ldm_x4(t4, sbs + BLO + rb);
                bl[tp*2][0]=t4[0]; bl[tp*2][1]=t4[1]; bl[tp*2+1][0]=t4[2]; bl[tp*2+1][1]=t4[3];
            }
#pragma unroll
            for (int mt=0; mt<MT; ++mt)
#pragma unroll
                for (int nt=0; nt<NTL; ++nt)
                    mma_bf16(acc[mt][nt], ah[mt], bh[nt]);
#pragma unroll
            for (int mt=0; mt<MT; ++mt)
#pragma unroll
                for (int nt=0; nt<NTL; ++nt)
                    mma_bf16(acc[mt][nt], ah[mt], bl[nt]);
#pragma unroll
            for (int mt=0; mt<MT; ++mt)
#pragma unroll
                for (int nt=0; nt<NTL; ++nt)
                    mma_bf16(acc[mt][nt], al[mt], bh[nt]);
        }
        __syncthreads();   // stage c consumed; safe to overwrite next iter
    }

    const int cr = lane>>2;
    const int cc = (lane&3)*2;
#pragma unroll
    for (int mt=0; mt<MT; ++mt){
        const int rbase = m0 + wm0 + mt*16 + cr;
#pragma unroll
        for (int nt=0; nt<NTL; ++nt){
            const int col = n0 + wn0 + nt*8 + cc;
            float2 v0; v0.x = acc[mt][nt][0]; v0.y = acc[mt][nt][1];
            float2 v1; v1.x = acc[mt][nt][2]; v1.y = acc[mt][nt][3];
            *reinterpret_cast<float2*>(C + (size_t)rbase*ldc + col)     = v0;
            *reinterpret_cast<float2*>(C + (size_t)(rbase+8)*ldc + col) = v1;
        }
    }
}

// ---------------------------------------------------------------------------
// Depthwise causal conv (k=4) + bias + silu; writes xc as bf16 hi/lo planes.
// ---------------------------------------------------------------------------
__global__ void __launch_bounds__(256) conv_kernel(
    const float* __restrict__ xz,
    const float* __restrict__ cw, const float* __restrict__ cb,
    __nv_bfloat16* __restrict__ xc_hi, __nv_bfloat16* __restrict__ xc_lo)
{
    const int flat = blockIdx.x*256 + threadIdx.x;
    const int d   = flat & (DI-1);
    const int t   = (flat >> 10) & (LL-1);
    const int b   = (flat >> 20) & (BB-1);
    const int dir = flat >> 23;

    float acc = cb[d];
    const float w0=cw[d*4+0], w1=cw[d*4+1], w2=cw[d*4+2], w3=cw[d*4+3];
    const float* src = xz + ((size_t)b*LL)*(2*DI) + d;
#pragma unroll
    for (int j=0;j<4;j++){
        const int tt = t - 3 + j;
        if (tt >= 0){
            const int st = dir ? (LL-1-tt) : tt;
            const float wj = (j==0)?w0:(j==1)?w1:(j==2)?w2:w3;
            acc += wj * src[(size_t)st*(2*DI)];
        }
    }
    acc = silu_fast(acc);
    __nv_bfloat16 hv, lv;
    split_bf16(acc, hv, lv);
    const size_t idx = (size_t)dir*NT*DI + ((size_t)(b*LL+t))*DI + d;
    xc_hi[idx] = hv;
    xc_lo[idx] = lv;
}

// ---------------------------------------------------------------------------
// Selective scan, 2 threads per channel (8 states each), fused dt projection.
// Reads u from xc hi/lo planes; writes y as bf16 hi/lo planes.
// Grid: 2 dir x 8 batch x 16 d-chunks(64ch) = 256 blocks, 128 threads.
// ---------------------------------------------------------------------------
#define TTILE 16
__global__ void __launch_bounds__(128) scan_kernel(
    const __nv_bfloat16* __restrict__ xc_hi, const __nv_bfloat16* __restrict__ xc_lo,
    const float* __restrict__ xdbl, const float* __restrict__ xz,
    const float* __restrict__ A_log,const float* __restrict__ Dp,
    const float* __restrict__ dtw,  const float* __restrict__ dtb,
    __nv_bfloat16* __restrict__ y_hi, __nv_bfloat16* __restrict__ y_lo)
{
    __shared__ float su [TTILE][64];
    __shared__ float sz [TTILE][64];
    __shared__ float sXD[TTILE][64];

    const int bx  = blockIdx.x;
    const int dir = bx >> 7;
    const int b   = (bx >> 4) & 7;
    const int dch = bx & 15;
    const int tid = threadIdx.x;
    const int c    = tid >> 1;
    const int half = tid & 1;
    const int d    = dch*64 + c;
    const int noff = half*8;

    float a[8], h[8];
#pragma unroll
    for (int j=0;j<8;j++){
        a[j] = -expf(A_log[(size_t)d*NSTATE + noff + j]);
        h[j] = 0.f;
    }
    const float a0 = -expf(A_log[(size_t)d*NSTATE]);
    unsigned ok = 1u;
#pragma unroll
    for (int j=0;j<8;j++){
        const float expect = a0*(float)(noff+j+1);
        ok &= (fabsf(a[j] - expect) <= 1e-4f*fabsf(a[j])) ? 1u : 0u;
    }
    ok &= __shfl_xor_sync(0xffffffffu, ok, 1);
    const bool fast = (ok != 0u);
    const float Dv = Dp[d];

    float w[16];
#pragma unroll
    for (int r=0;r<16;r++) w[r] = dtw[(size_t)d*RK + half*16 + r];
    const float bias = dtb[d];

    const size_t cb = (size_t)dir*NT*DI + (size_t)b*LL*DI + (size_t)dch*64;
    const __nv_bfloat16* xch = xc_hi + cb;
    const __nv_bfloat16* xcl = xc_lo + cb;
    __nv_bfloat16* yph = y_hi + cb;
    __nv_bfloat16* ypl = y_lo + cb;
    const float* xdp = xdbl + ((size_t)dir*NT + (size_t)b*LL)*64;
    const float* zp  = xz + (size_t)b*LL*(2*DI) + DI + (size_t)dch*64;

    for (int t0=0; t0<LL; t0+=TTILE){
        __syncthreads();
#pragma unroll
        for (int k=0;k<8;k++){
            const int idx = tid + k*128;
            const int row = idx>>6, col = idx&63;
            const int t = t0 + row;
            su [row][col] = __bfloat162float(xch[(size_t)t*DI + col])
                          + __bfloat162float(xcl[(size_t)t*DI + col]);
            sXD[row][col] = xdp[(size_t)t*64 + col];
            const int zt = dir ? (LL-1-t) : t;
            sz [row][col] = zp[(size_t)zt*(2*DI) + col];
        }
        __syncthreads();

        float dtv[TTILE];
#pragma unroll
        for (int i=0;i<TTILE;i++){
            float s0=0.f,s1=0.f,s2=0.f,s3=0.f;
            const float* xr = &sXD[i][half*16];
#pragma unroll
            for (int r=0;r<16;r+=4){
                s0 += xr[r+0]*w[r+0];
                s1 += xr[r+1]*w[r+1];
                s2 += xr[r+2]*w[r+2];
                s3 += xr[r+3]*w[r+3];
            }
            float v = (s0+s1)+(s2+s3);
            v += __shfl_xor_sync(0xffffffffu, v, 1);
            v += bias;
            dtv[i] = (v > 20.f) ? v : __logf(1.f + __expf(v));
        }

        if (fast){
#pragma unroll
            for (int i=0;i<TTILE;i++){
                const float dt  = dtv[i];
                const float u   = su[i][c];
                const float dtu = dt * u;
                const float rr  = __expf(dt * a0);
                const float r2 = rr*rr, r4 = r2*r2;
                const float r3 = r2*rr, r5 = r4*rr, r6 = r4*r2, r7 = r4*r3, r8 = r4*r4;
                const float base = half ? r8 : 1.f;
                const float p[8] = {base*rr, base*r2, base*r3, base*r4,
                                    base*r5, base*r6, base*r7, base*r8};
                float y0=0.f, y1=0.f;
#pragma unroll
                for (int j=0;j<8;j++){
                    h[j] = p[j]*h[j] + dtu * sXD[i][32+noff+j];
                    const float cterm = h[j] * sXD[i][48+noff+j];
                    if (j&1) y1 += cterm; else y0 += cterm;
                }
                float ys = y0 + y1;
                ys += __shfl_xor_sync(0xffffffffu, ys, 1);
                if (half==0){
                    const float y = (u*Dv + ys) * silu_fast(sz[i][c]);
                    __nv_bfloat16 hv, lv;
                    split_bf16(y, hv, lv);
                    yph[(size_t)(t0+i)*DI + c] = hv;
                    ypl[(size_t)(t0+i)*DI + c] = lv;
                }
            }
        } else {
#pragma unroll
            for (int i=0;i<TTILE;i++){
                const float dt  = dtv[i];
                const float u   = su[i][c];
                const float dtu = dt * u;
                float y0=0.f, y1=0.f;
#pragma unroll
                for (int j=0;j<8;j++){
                    const float dA = __expf(dt * a[j]);
                    h[j] = dA*h[j] + dtu * sXD[i][32+noff+j];
                    const float cterm = h[j] * sXD[i][48+noff+j];
                    if (j&1) y1 += cterm; else y0 += cterm;
                }
                float ys = y0 + y1;
                ys += __shfl_xor_sync(0xffffffffu, ys, 1);
                if (half==0){
                    const float y = (u*Dv + ys) * silu_fast(sz[i][c]);
                    __nv_bfloat16 hv, lv;
                    split_bf16(y, hv, lv);
                    yph[(size_t)(t0+i)*DI + c] = hv;
                    ypl[(size_t)(t0+i)*DI + c] = lv;
                }
            }
        }
    }
}

// ---------------------------------------------------------------------------
// Final output: hidden[b,t,:] = o_fwd[b,t,:] + o_bwd[b,L-1-t,:]
// ---------------------------------------------------------------------------
__global__ void __launch_bounds__(256) add_kernel(
    const float* __restrict__ o, float* __restrict__ dst)
{
    const int flat = blockIdx.x*256 + threadIdx.x;
    const int e = flat & (DM-1);
    const int t = (flat >> 9) & (LL-1);
    const int b = flat >> 19;
    const int tok  = b*LL + t;
    const int tokb = b*LL + (LL-1-t);
    dst[flat] = o[(size_t)tok*DM + e] + o[(size_t)(NT + tokb)*DM + e];
}

// ---------------------------------------------------------------------------
// Launch
// ---------------------------------------------------------------------------
extern "C" void kernel_launch(void* const* d_in, const int* in_sizes, int n_in,
                              void* d_out, int out_size)
{
    (void)in_sizes; (void)n_in; (void)out_size;
    const float* x      = (const float*)d_in[0];
    const float* norm_w = (const float*)d_in[1];
    const float* norm_b = (const float*)d_in[2];
    const float* in_w   = (const float*)d_in[3];
    const float* conv_w = (const float*)d_in[4];
    const float* conv_b = (const float*)d_in[5];
    const float* xp_w   = (const float*)d_in[6];
    const float* dtp_w  = (const float*)d_in[7];
    const float* dtp_b  = (const float*)d_in[8];
    const float* A_log  = (const float*)d_in[9];
    const float* Dp     = (const float*)d_in[10];
    const float* out_w  = (const float*)d_in[11];
    float* dout = (float*)d_out;

    float *resid,*xz,*xdbl,*ob;
    __nv_bfloat16 *hhi,*hlo,*xchi,*xclo,*yhi,*ylo;
    __nv_bfloat16 *w1hi,*w1lo,*w2hi,*w2lo,*w4hi,*w4lo;
    cudaGetSymbolAddress((void**)&resid, g_resid);
    cudaGetSymbolAddress((void**)&xz,    g_xz);
    cudaGetSymbolAddress((void**)&xdbl,  g_xdbl);
    cudaGetSymbolAddress((void**)&ob,    g_o);
    cudaGetSymbolAddress((void**)&hhi,   g_h_hi);
    cudaGetSymbolAddress((void**)&hlo,   g_h_lo);
    cudaGetSymbolAddress((void**)&xchi,  g_xc_hi);
    cudaGetSymbolAddress((void**)&xclo,  g_xc_lo);
    cudaGetSymbolAddress((void**)&yhi,   g_y_hi);
    cudaGetSymbolAddress((void**)&ylo,   g_y_lo);
    cudaGetSymbolAddress((void**)&w1hi,  g_w1_hi);
    cudaGetSymbolAddress((void**)&w1lo,  g_w1_lo);
    cudaGetSymbolAddress((void**)&w2hi,  g_w2_hi);
    cudaGetSymbolAddress((void**)&w2lo,  g_w2_lo);
    cudaGetSymbolAddress((void**)&w4hi,  g_w4_hi);
    cudaGetSymbolAddress((void**)&w4lo,  g_w4_lo);

    constexpr int SMEM_BIG = 2*(2*128*80 + 2*128*80);   // 81920 (128x128)
    constexpr int SMEM_MED = 2*(2*128*80 + 2*64*80);    // 61440 (128x64)
    static bool attr_done = false;
    if (!attr_done){
        cudaFuncSetAttribute((const void*)gemm_bf16_kernel<128,128>,
                             cudaFuncAttributeMaxDynamicSharedMemorySize, SMEM_BIG);
        cudaFuncSetAttribute((const void*)gemm_bf16_kernel<128,64>,
                             cudaFuncAttributeMaxDynamicSharedMemorySize, SMEM_MED);
        attr_done = true;
    }

    // weight conversion (whole-tensor, all layers)
    {
        const int n1 = DEPTH*2*DI*DM/4, n2 = DEPTH*64*DI/4, n4 = DEPTH*DM*DI/4;
        wcvt_kernel<<<(n1+255)/256,256>>>(in_w,  w1hi, w1lo, n1);
        wcvt_kernel<<<(n2+255)/256,256>>>(xp_w,  w2hi, w2lo, n2);
        wcvt_kernel<<<(n4+255)/256,256>>>(out_w, w4hi, w4lo, n4);
    }

    for (int i=0;i<DEPTH;i++){
        ln_kernel<<<NT,128>>>( (i==0)? x : resid, (i==0)? (const float*)nullptr : ob,
                               resid, norm_w + i*DM, norm_b + i*DM, hhi, hlo );

        // GEMM1: xz[8192,2048] = h @ in_w^T
        gemm_bf16_kernel<128,128><<<dim3(2048/128, 8192/128), 256, SMEM_BIG>>>(
            hhi, hlo, DM, w1hi + (size_t)i*2*DI*DM, w1lo + (size_t)i*2*DI*DM, DM,
            xz, 2*DI);

        conv_kernel<<<(2*NT*DI)/256,256>>>(xz, conv_w + i*DI*4, conv_b + i*DI,
                                           xchi, xclo);

        // GEMM2: xdbl[16384,64] = xc @ xp_w^T
        gemm_bf16_kernel<128,64><<<dim3(1, 16384/128), 256, SMEM_MED>>>(
            xchi, xclo, DI, w2hi + (size_t)i*64*DI, w2lo + (size_t)i*64*DI, DI,
            xdbl, 64);

        scan_kernel<<<256,128>>>(xchi, xclo, xdbl, xz,
                                 A_log + (size_t)i*DI*NSTATE, Dp + i*DI,
                                 dtp_w + (size_t)i*DI*RK, dtp_b + i*DI, yhi, ylo);

        // GEMM4: o[16384,512] = y @ out_w^T
        gemm_bf16_kernel<128,128><<<dim3(512/128, 16384/128), 256, SMEM_BIG>>>(
            yhi, ylo, DI, w4hi + (size_t)i*DM*DI, w4lo + (size_t)i*DM*DI, DI,
            ob, DM);
    }
    add_kernel<<<(NT*DM)/256,256>>>(ob, dout);
}

// round 8
// speedup vs baseline: 1.1553x; 1.0949x over previous
#include <cuda_runtime.h>
#include <cuda_bf16.h>
#include <cstdint>
#include <cstddef>

// ---------------------------------------------------------------------------
// Problem constants
// ---------------------------------------------------------------------------
#define BB      8
#define LL      1024
#define DM      512
#define DI      1024
#define NSTATE  16
#define RK      32
#define NT      (BB*LL)          // 8192 tokens
#define DEPTH   4

// ---------------------------------------------------------------------------
// Scratch buffers
// ---------------------------------------------------------------------------
__device__ float         g_resid[NT*DM];
__device__ __nv_bfloat16 g_h_hi [NT*DM];
__device__ __nv_bfloat16 g_h_lo [NT*DM];
__device__ float         g_xz   [NT*2*DI];
__device__ __nv_bfloat16 g_xc_hi[2*NT*DI];
__device__ __nv_bfloat16 g_xc_lo[2*NT*DI];
__device__ float         g_xdbl [2*NT*64];
__device__ __nv_bfloat16 g_y_hi [2*NT*DI];
__device__ __nv_bfloat16 g_y_lo [2*NT*DI];
__device__ float         g_o    [2*NT*DM];
// converted weights (hi/lo planes), all layers
__device__ __nv_bfloat16 g_w1_hi[DEPTH*2*DI*DM];
__device__ __nv_bfloat16 g_w1_lo[DEPTH*2*DI*DM];
__device__ __nv_bfloat16 g_w2_hi[DEPTH*64*DI];
__device__ __nv_bfloat16 g_w2_lo[DEPTH*64*DI];
__device__ __nv_bfloat16 g_w4_hi[DEPTH*DM*DI];
__device__ __nv_bfloat16 g_w4_lo[DEPTH*DM*DI];

// ---------------------------------------------------------------------------
// Helpers
// ---------------------------------------------------------------------------
__device__ __forceinline__ uint32_t smem_u32(const void* p){
    uint32_t a;
    asm("{ .reg .u64 t; cvta.to.shared.u64 t, %1; cvt.u32.u64 %0, t; }" : "=r"(a) : "l"(p));
    return a;
}
__device__ __forceinline__ float warpReduceSum(float v){
#pragma unroll
    for (int o=16;o>0;o>>=1) v += __shfl_xor_sync(0xffffffffu, v, o);
    return v;
}
__device__ __forceinline__ float silu_fast(float x){
    return x / (1.f + __expf(-x));
}
__device__ __forceinline__ void ldm_x4(uint32_t* r, uint32_t addr){
    asm volatile("ldmatrix.sync.aligned.m8n8.x4.shared.b16 {%0,%1,%2,%3}, [%4];"
        : "=r"(r[0]), "=r"(r[1]), "=r"(r[2]), "=r"(r[3]) : "r"(addr));
}
__device__ __forceinline__ void mma_bf16(float* c, const uint32_t* a, const uint32_t* b){
    asm volatile(
        "mma.sync.aligned.m16n8k16.row.col.f32.bf16.bf16.f32 "
        "{%0,%1,%2,%3}, {%4,%5,%6,%7}, {%8,%9}, {%0,%1,%2,%3};"
        : "+f"(c[0]), "+f"(c[1]), "+f"(c[2]), "+f"(c[3])
        : "r"(a[0]), "r"(a[1]), "r"(a[2]), "r"(a[3]), "r"(b[0]), "r"(b[1]));
}
__device__ __forceinline__ void cp_async16(uint32_t dst, const void* src){
    asm volatile("cp.async.cg.shared.global [%0], [%1], 16;" :: "r"(dst), "l"(src));
}
__device__ __forceinline__ void cp_commit(){
    asm volatile("cp.async.commit_group;");
}
template<int N>
__device__ __forceinline__ void cp_wait(){
    asm volatile("cp.async.wait_group %0;" :: "n"(N));
}
__device__ __forceinline__ void split_bf16(float v, __nv_bfloat16& hi, __nv_bfloat16& lo){
    hi = __float2bfloat16(v);
    lo = __float2bfloat16(v - __bfloat162float(hi));
}

// ---------------------------------------------------------------------------
// Weight conversion: fp32 -> hi/lo bf16 planes (float4 granularity)
// ---------------------------------------------------------------------------
__global__ void __launch_bounds__(256) wcvt_kernel(
    const float* __restrict__ src,
    __nv_bfloat16* __restrict__ hi, __nv_bfloat16* __restrict__ lo, int n4)
{
    const int i = blockIdx.x*256 + threadIdx.x;
    if (i >= n4) return;
    float4 v = reinterpret_cast<const float4*>(src)[i];
    __nv_bfloat162 h0 = __floats2bfloat162_rn(v.x, v.y);
    __nv_bfloat162 h1 = __floats2bfloat162_rn(v.z, v.w);
    float2 f0 = __bfloat1622float2(h0);
    float2 f1 = __bfloat1622float2(h1);
    __nv_bfloat162 l0 = __floats2bfloat162_rn(v.x - f0.x, v.y - f0.y);
    __nv_bfloat162 l1 = __floats2bfloat162_rn(v.z - f1.x, v.w - f1.y);
    uint2 hw, lw;
    hw.x = *reinterpret_cast<uint32_t*>(&h0); hw.y = *reinterpret_cast<uint32_t*>(&h1);
    lw.x = *reinterpret_cast<uint32_t*>(&l0); lw.y = *reinterpret_cast<uint32_t*>(&l1);
    reinterpret_cast<uint2*>(hi)[i] = hw;
    reinterpret_cast<uint2*>(lo)[i] = lw;
}

// ---------------------------------------------------------------------------
// LayerNorm + residual (+ fused bidirectional add); writes h as bf16 planes.
// ---------------------------------------------------------------------------
__global__ void __launch_bounds__(128) ln_kernel(
    const float* __restrict__ src0, const float* __restrict__ o,
    float* __restrict__ resid,
    const float* __restrict__ w, const float* __restrict__ b,
    __nv_bfloat16* __restrict__ h_hi, __nv_bfloat16* __restrict__ h_lo)
{
    __shared__ float sm[8];
    const int row = blockIdx.x, tid = threadIdx.x;
    float4 v = reinterpret_cast<const float4*>(src0 + (size_t)row*DM)[tid];
    if (o){
        const int t    = row & (LL-1);
        const int tokb = (row - t) + (LL-1 - t);
        float4 u1 = reinterpret_cast<const float4*>(o + (size_t)row*DM)[tid];
        float4 u2 = reinterpret_cast<const float4*>(o + (size_t)(NT + tokb)*DM)[tid];
        v.x += u1.x+u2.x; v.y += u1.y+u2.y; v.z += u1.z+u2.z; v.w += u1.w+u2.w;
    }
    reinterpret_cast<float4*>(resid + (size_t)row*DM)[tid] = v;

    float s = v.x+v.y+v.z+v.w;
    s = warpReduceSum(s);
    const int wid = tid>>5, lane = tid&31;
    if (lane==0) sm[wid]=s;
    __syncthreads();
    const float mu = (sm[0]+sm[1]+sm[2]+sm[3]) * (1.f/(float)DM);
    const float dx=v.x-mu, dy=v.y-mu, dz=v.z-mu, dw=v.w-mu;
    float q = dx*dx+dy*dy+dz*dz+dw*dw;
    q = warpReduceSum(q);
    if (lane==0) sm[4+wid]=q;
    __syncthreads();
    const float var = (sm[4]+sm[5]+sm[6]+sm[7]) * (1.f/(float)DM);
    const float rs = rsqrtf(var + 1e-5f);
    const float4 wv = reinterpret_cast<const float4*>(w)[tid];
    const float4 bv = reinterpret_cast<const float4*>(b)[tid];
    float4 ov;
    ov.x = dx*rs*wv.x + bv.x;
    ov.y = dy*rs*wv.y + bv.y;
    ov.z = dz*rs*wv.z + bv.z;
    ov.w = dw*rs*wv.w + bv.w;
    __nv_bfloat162 h0 = __floats2bfloat162_rn(ov.x, ov.y);
    __nv_bfloat162 h1 = __floats2bfloat162_rn(ov.z, ov.w);
    float2 f0 = __bfloat1622float2(h0);
    float2 f1 = __bfloat1622float2(h1);
    __nv_bfloat162 l0 = __floats2bfloat162_rn(ov.x - f0.x, ov.y - f0.y);
    __nv_bfloat162 l1 = __floats2bfloat162_rn(ov.z - f1.x, ov.w - f1.y);
    uint2 hw, lw;
    hw.x = *reinterpret_cast<uint32_t*>(&h0); hw.y = *reinterpret_cast<uint32_t*>(&h1);
    lw.x = *reinterpret_cast<uint32_t*>(&l0); lw.y = *reinterpret_cast<uint32_t*>(&l1);
    reinterpret_cast<uint2*>(h_hi + (size_t)row*DM)[tid] = hw;
    reinterpret_cast<uint2*>(h_lo + (size_t)row*DM)[tid] = lw;
}

// ---------------------------------------------------------------------------
// Split-bf16 MMA GEMM over precomputed hi/lo planes.
// 128 threads, 4 warps in 2x2 grid, warp tile (BM/2)x(BN/2).
// cp.async 2-stage pipeline, term-major MMA order, row pitch 80B.
// ---------------------------------------------------------------------------
template<int BM,int BN>
__global__ void __launch_bounds__(128) gemm_bf16_kernel(
    const __nv_bfloat16* __restrict__ Ahi, const __nv_bfloat16* __restrict__ Alo, int lda,
    const __nv_bfloat16* __restrict__ Whi, const __nv_bfloat16* __restrict__ Wlo, int K,
    float* __restrict__ C, int ldc)
{
    constexpr int WM  = BM/2;
    constexpr int WN  = BN/2;
    constexpr int MT  = WM/16;
    constexpr int NTL = WN/8;
    constexpr int AHI = 0;
    constexpr int ALO = BM*80;
    constexpr int BHI = 2*BM*80;
    constexpr int BLO = BHI + BN*80;
    constexpr int STAGE = BHI + 2*BN*80;

    extern __shared__ __align__(16) char smem[];
    const uint32_t sb = smem_u32(smem);

    const int tid  = threadIdx.x;
    const int wid  = tid>>5, lane = tid&31;
    const int m0   = blockIdx.y*BM, n0 = blockIdx.x*BN;
    const int wm0  = (wid>>1)*WM;
    const int wn0  = (wid&1)*WN;

    float acc[MT][NTL][4];
#pragma unroll
    for (int i=0;i<MT;i++)
#pragma unroll
        for (int j=0;j<NTL;j++)
#pragma unroll
            for (int q=0;q<4;q++) acc[i][j][q]=0.f;

    const int a_row = (lane&7) + ((lane>>3)&1)*8;
    const int a_kb  = (lane>>4)*16;
    const int b_row = (lane&7) + (lane>>4)*8;
    const int b_kb  = ((lane>>3)&1)*16;

    // stage loader: 16B chunk = 8 bf16; BK=32 -> 4 chunks per row-plane
    auto issue_stage = [&](int s, int k0){
        const uint32_t base = sb + (uint32_t)(s*STAGE);
#pragma unroll
        for (int u=0; u<BM/32; ++u){
            const int id = tid + u*128;
            const int r = id>>2, q = id&3;
            const size_t go = (size_t)(m0+r)*lda + k0 + q*8;
            cp_async16(base + AHI + r*80 + q*16, Ahi + go);
            cp_async16(base + ALO + r*80 + q*16, Alo + go);
        }
#pragma unroll
        for (int u=0; u<BN/32; ++u){
            const int id = tid + u*128;
            const int r = id>>2, q = id&3;
            const size_t go = (size_t)(n0+r)*K + k0 + q*8;
            cp_async16(base + BHI + r*80 + q*16, Whi + go);
            cp_async16(base + BLO + r*80 + q*16, Wlo + go);
        }
        cp_commit();
    };

    const int nchunk = K >> 5;
    issue_stage(0, 0);

    for (int c=0; c<nchunk; ++c){
        if (c+1 < nchunk){
            issue_stage((c+1)&1, (c+1)*32);   // buffer freed by trailing sync of iter c-1
            cp_wait<1>();
        } else {
            cp_wait<0>();
        }
        __syncthreads();
        const uint32_t sbs = sb + (uint32_t)((c&1)*STAGE);
#pragma unroll
        for (int ks=0; ks<2; ++ks){
            uint32_t ah[MT][4], al[MT][4];
#pragma unroll
            for (int mt=0; mt<MT; ++mt){
                const uint32_t ra = (uint32_t)((wm0 + mt*16 + a_row)*80 + ks*32 + a_kb);
                ldm_x4(ah[mt], sbs + AHI + ra);
                ldm_x4(al[mt], sbs + ALO + ra);
            }
            uint32_t bh[NTL][2], bl[NTL][2];
#pragma unroll
            for (int tp=0; tp<NTL/2; ++tp){
                const uint32_t rb = (uint32_t)((wn0 + tp*16 + b_row)*80 + ks*32 + b_kb);
                uint32_t t4[4];
                ldm_x4(t4, sbs + BHI + rb);
                bh[tp*2][0]=t4[0]; bh[tp*2][1]=t4[1]; bh[tp*2+1][0]=t4[2]; bh[tp*2+1][1]=t4[3];
                ldm_x4(t4, sbs + BLO + rb);
                bl[tp*2][0]=t4[0]; bl[tp*2][1]=t4[1]; bl[tp*2+1][0]=t4[2]; bl[tp*2+1][1]=t4[3];
            }
#pragma unroll
            for (int mt=0; mt<MT; ++mt)
#pragma unroll
                for (int nt=0; nt<NTL; ++nt)
                    mma_bf16(acc[mt][nt], ah[mt], bh[nt]);
#pragma unroll
            for (int mt=0; mt<MT; ++mt)
#pragma unroll
                for (int nt=0; nt<NTL; ++nt)
                    mma_bf16(acc[mt][nt], ah[mt], bl[nt]);
#pragma unroll
            for (int mt=0; mt<MT; ++mt)
#pragma unroll
                for (int nt=0; nt<NTL; ++nt)
                    mma_bf16(acc[mt][nt], al[mt], bh[nt]);
        }
        __syncthreads();   // stage c consumed; safe to overwrite next iter
    }

    const int cr = lane>>2;
    const int cc = (lane&3)*2;
#pragma unroll
    for (int mt=0; mt<MT; ++mt){
        const int rbase = m0 + wm0 + mt*16 + cr;
#pragma unroll
        for (int nt=0; nt<NTL; ++nt){
            const int col = n0 + wn0 + nt*8 + cc;
            float2 v0; v0.x = acc[mt][nt][0]; v0.y = acc[mt][nt][1];
            float2 v1; v1.x = acc[mt][nt][2]; v1.y = acc[mt][nt][3];
            *reinterpret_cast<float2*>(C + (size_t)rbase*ldc + col)     = v0;
            *reinterpret_cast<float2*>(C + (size_t)(rbase+8)*ldc + col) = v1;
        }
    }
}

// ---------------------------------------------------------------------------
// Depthwise causal conv (k=4) + bias + silu; writes xc as bf16 hi/lo planes.
// ---------------------------------------------------------------------------
__global__ void __launch_bounds__(256) conv_kernel(
    const float* __restrict__ xz,
    const float* __restrict__ cw, const float* __restrict__ cb,
    __nv_bfloat16* __restrict__ xc_hi, __nv_bfloat16* __restrict__ xc_lo)
{
    const int flat = blockIdx.x*256 + threadIdx.x;
    const int d   = flat & (DI-1);
    const int t   = (flat >> 10) & (LL-1);
    const int b   = (flat >> 20) & (BB-1);
    const int dir = flat >> 23;

    float acc = cb[d];
    const float w0=cw[d*4+0], w1=cw[d*4+1], w2=cw[d*4+2], w3=cw[d*4+3];
    const float* src = xz + ((size_t)b*LL)*(2*DI) + d;
#pragma unroll
    for (int j=0;j<4;j++){
        const int tt = t - 3 + j;
        if (tt >= 0){
            const int st = dir ? (LL-1-tt) : tt;
            const float wj = (j==0)?w0:(j==1)?w1:(j==2)?w2:w3;
            acc += wj * src[(size_t)st*(2*DI)];
        }
    }
    acc = silu_fast(acc);
    __nv_bfloat16 hv, lv;
    split_bf16(acc, hv, lv);
    const size_t idx = (size_t)dir*NT*DI + ((size_t)(b*LL+t))*DI + d;
    xc_hi[idx] = hv;
    xc_lo[idx] = lv;
}

// ---------------------------------------------------------------------------
// Selective scan, 2 threads per channel (8 states each), fused dt projection.
// ---------------------------------------------------------------------------
#define TTILE 16
__global__ void __launch_bounds__(128) scan_kernel(
    const __nv_bfloat16* __restrict__ xc_hi, const __nv_bfloat16* __restrict__ xc_lo,
    const float* __restrict__ xdbl, const float* __restrict__ xz,
    const float* __restrict__ A_log,const float* __restrict__ Dp,
    const float* __restrict__ dtw,  const float* __restrict__ dtb,
    __nv_bfloat16* __restrict__ y_hi, __nv_bfloat16* __restrict__ y_lo)
{
    __shared__ float su [TTILE][64];
    __shared__ float sz [TTILE][64];
    __shared__ float sXD[TTILE][64];

    const int bx  = blockIdx.x;
    const int dir = bx >> 7;
    const int b   = (bx >> 4) & 7;
    const int dch = bx & 15;
    const int tid = threadIdx.x;
    const int c    = tid >> 1;
    const int half = tid & 1;
    const int d    = dch*64 + c;
    const int noff = half*8;

    float a[8], h[8];
#pragma unroll
    for (int j=0;j<8;j++){
        a[j] = -expf(A_log[(size_t)d*NSTATE + noff + j]);
        h[j] = 0.f;
    }
    const float a0 = -expf(A_log[(size_t)d*NSTATE]);
    unsigned ok = 1u;
#pragma unroll
    for (int j=0;j<8;j++){
        const float expect = a0*(float)(noff+j+1);
        ok &= (fabsf(a[j] - expect) <= 1e-4f*fabsf(a[j])) ? 1u : 0u;
    }
    ok &= __shfl_xor_sync(0xffffffffu, ok, 1);
    const bool fast = (ok != 0u);
    const float Dv = Dp[d];

    float w[16];
#pragma unroll
    for (int r=0;r<16;r++) w[r] = dtw[(size_t)d*RK + half*16 + r];
    const float bias = dtb[d];

    const size_t cb = (size_t)dir*NT*DI + (size_t)b*LL*DI + (size_t)dch*64;
    const __nv_bfloat16* xch = xc_hi + cb;
    const __nv_bfloat16* xcl = xc_lo + cb;
    __nv_bfloat16* yph = y_hi + cb;
    __nv_bfloat16* ypl = y_lo + cb;
    const float* xdp = xdbl + ((size_t)dir*NT + (size_t)b*LL)*64;
    const float* zp  = xz + (size_t)b*LL*(2*DI) + DI + (size_t)dch*64;

    for (int t0=0; t0<LL; t0+=TTILE){
        __syncthreads();
#pragma unroll
        for (int k=0;k<8;k++){
            const int idx = tid + k*128;
            const int row = idx>>6, col = idx&63;
            const int t = t0 + row;
            su [row][col] = __bfloat162float(xch[(size_t)t*DI + col])
                          + __bfloat162float(xcl[(size_t)t*DI + col]);
            sXD[row][col] = xdp[(size_t)t*64 + col];
            const int zt = dir ? (LL-1-t) : t;
            sz [row][col] = zp[(size_t)zt*(2*DI) + col];
        }
        __syncthreads();

        float dtv[TTILE];
#pragma unroll
        for (int i=0;i<TTILE;i++){
            float s0=0.f,s1=0.f,s2=0.f,s3=0.f;
            const float* xr = &sXD[i][half*16];
#pragma unroll
            for (int r=0;r<16;r+=4){
                s0 += xr[r+0]*w[r+0];
                s1 += xr[r+1]*w[r+1];
                s2 += xr[r+2]*w[r+2];
                s3 += xr[r+3]*w[r+3];
            }
            float v = (s0+s1)+(s2+s3);
            v += __shfl_xor_sync(0xffffffffu, v, 1);
            v += bias;
            dtv[i] = (v > 20.f) ? v : __logf(1.f + __expf(v));
        }

        if (fast){
#pragma unroll
            for (int i=0;i<TTILE;i++){
                const float dt  = dtv[i];
                const float u   = su[i][c];
                const float dtu = dt * u;
                const float rr  = __expf(dt * a0);
                const float r2 = rr*rr, r4 = r2*r2;
                const float r3 = r2*rr, r5 = r4*rr, r6 = r4*r2, r7 = r4*r3, r8 = r4*r4;
                const float base = half ? r8 : 1.f;
                const float p[8] = {base*rr, base*r2, base*r3, base*r4,
                                    base*r5, base*r6, base*r7, base*r8};
                float y0=0.f, y1=0.f;
#pragma unroll
                for (int j=0;j<8;j++){
                    h[j] = p[j]*h[j] + dtu * sXD[i][32+noff+j];
                    const float cterm = h[j] * sXD[i][48+noff+j];
                    if (j&1) y1 += cterm; else y0 += cterm;
                }
                float ys = y0 + y1;
                ys += __shfl_xor_sync(0xffffffffu, ys, 1);
                if (half==0){
                    const float y = (u*Dv + ys) * silu_fast(sz[i][c]);
                    __nv_bfloat16 hv, lv;
                    split_bf16(y, hv, lv);
                    yph[(size_t)(t0+i)*DI + c] = hv;
                    ypl[(size_t)(t0+i)*DI + c] = lv;
                }
            }
        } else {
#pragma unroll
            for (int i=0;i<TTILE;i++){
                const float dt  = dtv[i];
                const float u   = su[i][c];
                const float dtu = dt * u;
                float y0=0.f, y1=0.f;
#pragma unroll
                for (int j=0;j<8;j++){
                    const float dA = __expf(dt * a[j]);
                    h[j] = dA*h[j] + dtu * sXD[i][32+noff+j];
                    const float cterm = h[j] * sXD[i][48+noff+j];
                    if (j&1) y1 += cterm; else y0 += cterm;
                }
                float ys = y0 + y1;
                ys += __shfl_xor_sync(0xffffffffu, ys, 1);
                if (half==0){
                    const float y = (u*Dv + ys) * silu_fast(sz[i][c]);
                    __nv_bfloat16 hv, lv;
                    split_bf16(y, hv, lv);
                    yph[(size_t)(t0+i)*DI + c] = hv;
                    ypl[(size_t)(t0+i)*DI + c] = lv;
                }
            }
        }
    }
}

// ---------------------------------------------------------------------------
// Final output: hidden[b,t,:] = o_fwd[b,t,:] + o_bwd[b,L-1-t,:]
// ---------------------------------------------------------------------------
__global__ void __launch_bounds__(256) add_kernel(
    const float* __restrict__ o, float* __restrict__ dst)
{
    const int flat = blockIdx.x*256 + threadIdx.x;
    const int e = flat & (DM-1);
    const int t = (flat >> 9) & (LL-1);
    const int b = flat >> 19;
    const int tok  = b*LL + t;
    const int tokb = b*LL + (LL-1-t);
    dst[flat] = o[(size_t)tok*DM + e] + o[(size_t)(NT + tokb)*DM + e];
}

// ---------------------------------------------------------------------------
// Launch
// ---------------------------------------------------------------------------
extern "C" void kernel_launch(void* const* d_in, const int* in_sizes, int n_in,
                              void* d_out, int out_size)
{
    (void)in_sizes; (void)n_in; (void)out_size;
    const float* x      = (const float*)d_in[0];
    const float* norm_w = (const float*)d_in[1];
    const float* norm_b = (const float*)d_in[2];
    const float* in_w   = (const float*)d_in[3];
    const float* conv_w = (const float*)d_in[4];
    const float* conv_b = (const float*)d_in[5];
    const float* xp_w   = (const float*)d_in[6];
    const float* dtp_w  = (const float*)d_in[7];
    const float* dtp_b  = (const float*)d_in[8];
    const float* A_log  = (const float*)d_in[9];
    const float* Dp     = (const float*)d_in[10];
    const float* out_w  = (const float*)d_in[11];
    float* dout = (float*)d_out;

    float *resid,*xz,*xdbl,*ob;
    __nv_bfloat16 *hhi,*hlo,*xchi,*xclo,*yhi,*ylo;
    __nv_bfloat16 *w1hi,*w1lo,*w2hi,*w2lo,*w4hi,*w4lo;
    cudaGetSymbolAddress((void**)&resid, g_resid);
    cudaGetSymbolAddress((void**)&xz,    g_xz);
    cudaGetSymbolAddress((void**)&xdbl,  g_xdbl);
    cudaGetSymbolAddress((void**)&ob,    g_o);
    cudaGetSymbolAddress((void**)&hhi,   g_h_hi);
    cudaGetSymbolAddress((void**)&hlo,   g_h_lo);
    cudaGetSymbolAddress((void**)&xchi,  g_xc_hi);
    cudaGetSymbolAddress((void**)&xclo,  g_xc_lo);
    cudaGetSymbolAddress((void**)&yhi,   g_y_hi);
    cudaGetSymbolAddress((void**)&ylo,   g_y_lo);
    cudaGetSymbolAddress((void**)&w1hi,  g_w1_hi);
    cudaGetSymbolAddress((void**)&w1lo,  g_w1_lo);
    cudaGetSymbolAddress((void**)&w2hi,  g_w2_hi);
    cudaGetSymbolAddress((void**)&w2lo,  g_w2_lo);
    cudaGetSymbolAddress((void**)&w4hi,  g_w4_hi);
    cudaGetSymbolAddress((void**)&w4lo,  g_w4_lo);

    constexpr int SMEM_BIG = 2*(2*128*80 + 2*128*80);   // 81920 (128x128)
    constexpr int SMEM_MED = 2*(2*128*80 + 2*64*80);    // 61440 (128x64)
    static bool attr_done = false;
    if (!attr_done){
        cudaFuncSetAttribute((const void*)gemm_bf16_kernel<128,128>,
                             cudaFuncAttributeMaxDynamicSharedMemorySize, SMEM_BIG);
        cudaFuncSetAttribute((const void*)gemm_bf16_kernel<128,64>,
                             cudaFuncAttributeMaxDynamicSharedMemorySize, SMEM_MED);
        attr_done = true;
    }

    // weight conversion (whole-tensor, all layers)
    {
        const int n1 = DEPTH*2*DI*DM/4, n2 = DEPTH*64*DI/4, n4 = DEPTH*DM*DI/4;
        wcvt_kernel<<<(n1+255)/256,256>>>(in_w,  w1hi, w1lo, n1);
        wcvt_kernel<<<(n2+255)/256,256>>>(xp_w,  w2hi, w2lo, n2);
        wcvt_kernel<<<(n4+255)/256,256>>>(out_w, w4hi, w4lo, n4);
    }

    for (int i=0;i<DEPTH;i++){
        ln_kernel<<<NT,128>>>( (i==0)? x : resid, (i==0)? (const float*)nullptr : ob,
                               resid, norm_w + i*DM, norm_b + i*DM, hhi, hlo );

        // GEMM1: xz[8192,2048] = h @ in_w^T
        gemm_bf16_kernel<128,128><<<dim3(2048/128, 8192/128), 128, SMEM_BIG>>>(
            hhi, hlo, DM, w1hi + (size_t)i*2*DI*DM, w1lo + (size_t)i*2*DI*DM, DM,
            xz, 2*DI);

        conv_kernel<<<(2*NT*DI)/256,256>>>(xz, conv_w + i*DI*4, conv_b + i*DI,
                                           xchi, xclo);

        // GEMM2: xdbl[16384,64] = xc @ xp_w^T
        gemm_bf16_kernel<128,64><<<dim3(1, 16384/128), 128, SMEM_MED>>>(
            xchi, xclo, DI, w2hi + (size_t)i*64*DI, w2lo + (size_t)i*64*DI, DI,
            xdbl, 64);

        scan_kernel<<<256,128>>>(xchi, xclo, xdbl, xz,
                                 A_log + (size_t)i*DI*NSTATE, Dp + i*DI,
                                 dtp_w + (size_t)i*DI*RK, dtp_b + i*DI, yhi, ylo);

        // GEMM4: o[16384,512] = y @ out_w^T
        gemm_bf16_kernel<128,128><<<dim3(512/128, 16384/128), 128, SMEM_BIG>>>(
            yhi, ylo, DI, w4hi + (size_t)i*DM*DI, w4lo + (size_t)i*DM*DI, DI,
            ob, DM);
    }
    add_kernel<<<(NT*DM)/256,256>>>(ob, dout);
}

// round 9
// speedup vs baseline: 1.3564x; 1.1741x over previous
#include <cuda_runtime.h>
#include <cuda_fp16.h>
#include <cstdint>
#include <cstddef>

// ---------------------------------------------------------------------------
// Problem constants
// ---------------------------------------------------------------------------
#define BB      8
#define LL      1024
#define DM      512
#define DI      1024
#define NSTATE  16
#define RK      32
#define NT      (BB*LL)          // 8192 tokens
#define DEPTH   4

// ---------------------------------------------------------------------------
// Scratch buffers
// ---------------------------------------------------------------------------
__device__ float  g_resid[NT*DM];
__device__ __half g_h_hi [NT*DM];
__device__ __half g_h_lo [NT*DM];
__device__ float  g_xz   [NT*2*DI];
__device__ __half g_xc_hi[2*NT*DI];
__device__ __half g_xc_lo[2*NT*DI];
__device__ float  g_xdbl [2*NT*64];
__device__ __half g_y_hi [2*NT*DI];
__device__ __half g_y_lo [2*NT*DI];
__device__ float  g_o    [2*NT*DM];
// converted weights (single fp16 plane), all layers
__device__ __half g_w1[DEPTH*2*DI*DM];
__device__ __half g_w2[DEPTH*64*DI];
__device__ __half g_w4[DEPTH*DM*DI];

// ---------------------------------------------------------------------------
// Helpers
// ---------------------------------------------------------------------------
__device__ __forceinline__ uint32_t smem_u32(const void* p){
    uint32_t a;
    asm("{ .reg .u64 t; cvta.to.shared.u64 t, %1; cvt.u32.u64 %0, t; }" : "=r"(a) : "l"(p));
    return a;
}
__device__ __forceinline__ float warpReduceSum(float v){
#pragma unroll
    for (int o=16;o>0;o>>=1) v += __shfl_xor_sync(0xffffffffu, v, o);
    return v;
}
__device__ __forceinline__ float silu_fast(float x){
    return x / (1.f + __expf(-x));
}
__device__ __forceinline__ void ldm_x4(uint32_t* r, uint32_t addr){
    asm volatile("ldmatrix.sync.aligned.m8n8.x4.shared.b16 {%0,%1,%2,%3}, [%4];"
        : "=r"(r[0]), "=r"(r[1]), "=r"(r[2]), "=r"(r[3]) : "r"(addr));
}
__device__ __forceinline__ void mma_f16(float* c, const uint32_t* a, const uint32_t* b){
    asm volatile(
        "mma.sync.aligned.m16n8k16.row.col.f32.f16.f16.f32 "
        "{%0,%1,%2,%3}, {%4,%5,%6,%7}, {%8,%9}, {%0,%1,%2,%3};"
        : "+f"(c[0]), "+f"(c[1]), "+f"(c[2]), "+f"(c[3])
        : "r"(a[0]), "r"(a[1]), "r"(a[2]), "r"(a[3]), "r"(b[0]), "r"(b[1]));
}
__device__ __forceinline__ void cp_async16(uint32_t dst, const void* src){
    asm volatile("cp.async.cg.shared.global [%0], [%1], 16;" :: "r"(dst), "l"(src));
}
__device__ __forceinline__ void cp_commit(){
    asm volatile("cp.async.commit_group;");
}
template<int N>
__device__ __forceinline__ void cp_wait(){
    asm volatile("cp.async.wait_group %0;" :: "n"(N));
}
__device__ __forceinline__ void split_f16(float v, __half& hi, __half& lo){
    hi = __float2half_rn(v);
    lo = __float2half_rn(v - __half2float(hi));
}
__device__ __forceinline__ uint32_t pack_h2(__half a, __half b){
    __half2 h = __halves2half2(a, b);
    return *reinterpret_cast<uint32_t*>(&h);
}
// XOR chunk swizzle for 64B rows (4x16B chunks); conflict-free ldmatrix.
__device__ __forceinline__ uint32_t swz(int r, int q){
    return (uint32_t)(r*64 + ((q ^ ((r>>1)&3))<<4));
}

// ---------------------------------------------------------------------------
// Weight conversion: fp32 -> single fp16 plane
// ---------------------------------------------------------------------------
__global__ void __launch_bounds__(256) wcvt_kernel(
    const float* __restrict__ src, __half* __restrict__ dst, int n4)
{
    const int i = blockIdx.x*256 + threadIdx.x;
    if (i >= n4) return;
    float4 v = reinterpret_cast<const float4*>(src)[i];
    uint2 o;
    o.x = pack_h2(__float2half_rn(v.x), __float2half_rn(v.y));
    o.y = pack_h2(__float2half_rn(v.z), __float2half_rn(v.w));
    reinterpret_cast<uint2*>(dst)[i] = o;
}

// ---------------------------------------------------------------------------
// LayerNorm + residual (+ fused bidirectional add); writes h as fp16 planes.
// ---------------------------------------------------------------------------
__global__ void __launch_bounds__(128) ln_kernel(
    const float* __restrict__ src0, const float* __restrict__ o,
    float* __restrict__ resid,
    const float* __restrict__ w, const float* __restrict__ b,
    __half* __restrict__ h_hi, __half* __restrict__ h_lo)
{
    __shared__ float sm[8];
    const int row = blockIdx.x, tid = threadIdx.x;
    float4 v = reinterpret_cast<const float4*>(src0 + (size_t)row*DM)[tid];
    if (o){
        const int t    = row & (LL-1);
        const int tokb = (row - t) + (LL-1 - t);
        float4 u1 = reinterpret_cast<const float4*>(o + (size_t)row*DM)[tid];
        float4 u2 = reinterpret_cast<const float4*>(o + (size_t)(NT + tokb)*DM)[tid];
        v.x += u1.x+u2.x; v.y += u1.y+u2.y; v.z += u1.z+u2.z; v.w += u1.w+u2.w;
    }
    reinterpret_cast<float4*>(resid + (size_t)row*DM)[tid] = v;

    float s = v.x+v.y+v.z+v.w;
    s = warpReduceSum(s);
    const int wid = tid>>5, lane = tid&31;
    if (lane==0) sm[wid]=s;
    __syncthreads();
    const float mu = (sm[0]+sm[1]+sm[2]+sm[3]) * (1.f/(float)DM);
    const float dx=v.x-mu, dy=v.y-mu, dz=v.z-mu, dw=v.w-mu;
    float q = dx*dx+dy*dy+dz*dz+dw*dw;
    q = warpReduceSum(q);
    if (lane==0) sm[4+wid]=q;
    __syncthreads();
    const float var = (sm[4]+sm[5]+sm[6]+sm[7]) * (1.f/(float)DM);
    const float rs = rsqrtf(var + 1e-5f);
    const float4 wv = reinterpret_cast<const float4*>(w)[tid];
    const float4 bv = reinterpret_cast<const float4*>(b)[tid];
    float4 ov;
    ov.x = dx*rs*wv.x + bv.x;
    ov.y = dy*rs*wv.y + bv.y;
    ov.z = dz*rs*wv.z + bv.z;
    ov.w = dw*rs*wv.w + bv.w;
    __half hx,lx,hy,ly,hz,lz,hw2,lw2;
    split_f16(ov.x,hx,lx); split_f16(ov.y,hy,ly);
    split_f16(ov.z,hz,lz); split_f16(ov.w,hw2,lw2);
    uint2 H, L;
    H.x = pack_h2(hx,hy); H.y = pack_h2(hz,hw2);
    L.x = pack_h2(lx,ly); L.y = pack_h2(lz,lw2);
    reinterpret_cast<uint2*>(h_hi + (size_t)row*DM)[tid] = H;
    reinterpret_cast<uint2*>(h_lo + (size_t)row*DM)[tid] = L;
}

// ---------------------------------------------------------------------------
// fp16 2-term MMA GEMM: C = (Ahi + Alo) @ W^T, W pre-rounded to fp16.
// 128 threads, 4 warps 2x2, warp tile (BM/2)x(BN/2).
// 3-stage cp.async pipeline, ONE barrier per chunk, 64B swizzled rows.
// ---------------------------------------------------------------------------
template<int BM,int BN>
__global__ void __launch_bounds__(128) gemm_f16_kernel(
    const __half* __restrict__ Ahi, const __half* __restrict__ Alo, int lda,
    const __half* __restrict__ W, int K,
    float* __restrict__ C, int ldc)
{
    constexpr int WM  = BM/2;
    constexpr int WN  = BN/2;
    constexpr int MT  = WM/16;
    constexpr int NTL = WN/8;
    constexpr int AHI = 0;
    constexpr int ALO = BM*64;
    constexpr int BOF = 2*BM*64;
    constexpr int STAGE = 2*BM*64 + BN*64;

    extern __shared__ __align__(16) char smem[];
    const uint32_t sb = smem_u32(smem);

    const int tid  = threadIdx.x;
    const int wid  = tid>>5, lane = tid&31;
    const int m0   = blockIdx.y*BM, n0 = blockIdx.x*BN;
    const int wm0  = (wid>>1)*WM;
    const int wn0  = (wid&1)*WN;

    float acc[MT][NTL][4];
#pragma unroll
    for (int i=0;i<MT;i++)
#pragma unroll
        for (int j=0;j<NTL;j++)
#pragma unroll
            for (int q=0;q<4;q++) acc[i][j][q]=0.f;

    const int a_row = (lane&7) + ((lane>>3)&1)*8;
    const int aq    = lane>>4;         // 0/1 -> k chunk within ks half
    const int b_row = (lane&7) + (lane>>4)*8;
    const int bq    = (lane>>3)&1;

    auto issue_stage = [&](int s, int k0){
        const uint32_t base = sb + (uint32_t)(s*STAGE);
#pragma unroll
        for (int u=0; u<BM/32; ++u){
            const int id = tid + u*128;
            const int r = id>>2, q = id&3;
            const size_t go = (size_t)(m0+r)*lda + k0 + q*8;
            cp_async16(base + AHI + swz(r,q), Ahi + go);
            cp_async16(base + ALO + swz(r,q), Alo + go);
        }
#pragma unroll
        for (int u=0; u<BN/32; ++u){
            const int id = tid + u*128;
            const int r = id>>2, q = id&3;
            cp_async16(base + BOF + swz(r,q), W + (size_t)(n0+r)*K + k0 + q*8);
        }
        cp_commit();
    };

    const int nchunk = K >> 5;
    issue_stage(0, 0);
    issue_stage(1, 32);

    for (int c=0; c<nchunk; ++c){
        if (c+1 < nchunk) cp_wait<1>(); else cp_wait<0>();
        __syncthreads();                     // retires stage c-1 for all warps
        if (c+2 < nchunk) issue_stage((c+2)%3, (c+2)*32);

        const uint32_t sbs = sb + (uint32_t)((c%3)*STAGE);
#pragma unroll
        for (int ks=0; ks<2; ++ks){
            uint32_t ah[MT][4], al[MT][4];
#pragma unroll
            for (int mt=0; mt<MT; ++mt){
                const int row = wm0 + mt*16 + a_row;
                const uint32_t ra = swz(row, ks*2 + aq);
                ldm_x4(ah[mt], sbs + AHI + ra);
                ldm_x4(al[mt], sbs + ALO + ra);
            }
            uint32_t bh[NTL][2];
#pragma unroll
            for (int tp=0; tp<NTL/2; ++tp){
                const int row = wn0 + tp*16 + b_row;
                const uint32_t rb = swz(row, ks*2 + bq);
                uint32_t t4[4];
                ldm_x4(t4, sbs + BOF + rb);
                bh[tp*2][0]=t4[0]; bh[tp*2][1]=t4[1];
                bh[tp*2+1][0]=t4[2]; bh[tp*2+1][1]=t4[3];
            }
            // term-major: all hi-term MMAs, then all lo-term MMAs
#pragma unroll
            for (int mt=0; mt<MT; ++mt)
#pragma unroll
                for (int nt=0; nt<NTL; ++nt)
                    mma_f16(acc[mt][nt], ah[mt], bh[nt]);
#pragma unroll
            for (int mt=0; mt<MT; ++mt)
#pragma unroll
                for (int nt=0; nt<NTL; ++nt)
                    mma_f16(acc[mt][nt], al[mt], bh[nt]);
        }
    }

    const int cr = lane>>2;
    const int cc = (lane&3)*2;
#pragma unroll
    for (int mt=0; mt<MT; ++mt){
        const int rbase = m0 + wm0 + mt*16 + cr;
#pragma unroll
        for (int nt=0; nt<NTL; ++nt){
            const int col = n0 + wn0 + nt*8 + cc;
            float2 v0; v0.x = acc[mt][nt][0]; v0.y = acc[mt][nt][1];
            float2 v1; v1.x = acc[mt][nt][2]; v1.y = acc[mt][nt][3];
            *reinterpret_cast<float2*>(C + (size_t)rbase*ldc + col)     = v0;
            *reinterpret_cast<float2*>(C + (size_t)(rbase+8)*ldc + col) = v1;
        }
    }
}

// ---------------------------------------------------------------------------
// Depthwise causal conv (k=4) + bias + silu; writes xc as fp16 hi/lo planes.
// ---------------------------------------------------------------------------
__global__ void __launch_bounds__(256) conv_kernel(
    const float* __restrict__ xz,
    const float* __restrict__ cw, const float* __restrict__ cb,
    __half* __restrict__ xc_hi, __half* __restrict__ xc_lo)
{
    const int flat = blockIdx.x*256 + threadIdx.x;
    const int d   = flat & (DI-1);
    const int t   = (flat >> 10) & (LL-1);
    const int b   = (flat >> 20) & (BB-1);
    const int dir = flat >> 23;

    float acc = cb[d];
    const float w0=cw[d*4+0], w1=cw[d*4+1], w2=cw[d*4+2], w3=cw[d*4+3];
    const float* src = xz + ((size_t)b*LL)*(2*DI) + d;
#pragma unroll
    for (int j=0;j<4;j++){
        const int tt = t - 3 + j;
        if (tt >= 0){
            const int st = dir ? (LL-1-tt) : tt;
            const float wj = (j==0)?w0:(j==1)?w1:(j==2)?w2:w3;
            acc += wj * src[(size_t)st*(2*DI)];
        }
    }
    acc = silu_fast(acc);
    __half hv, lv;
    split_f16(acc, hv, lv);
    const size_t idx = (size_t)dir*NT*DI + ((size_t)(b*LL+t))*DI + d;
    xc_hi[idx] = hv;
    xc_lo[idx] = lv;
}

// ---------------------------------------------------------------------------
// Selective scan, 2 threads per channel (8 states each), fused dt projection.
// Reads u = hi+lo (exact); writes y as fp16 hi/lo planes.
// ---------------------------------------------------------------------------
#define TTILE 16
__global__ void __launch_bounds__(128) scan_kernel(
    const __half* __restrict__ xc_hi, const __half* __restrict__ xc_lo,
    const float* __restrict__ xdbl, const float* __restrict__ xz,
    const float* __restrict__ A_log,const float* __restrict__ Dp,
    const float* __restrict__ dtw,  const float* __restrict__ dtb,
    __half* __restrict__ y_hi, __half* __restrict__ y_lo)
{
    __shared__ float su [TTILE][64];
    __shared__ float sz [TTILE][64];
    __shared__ float sXD[TTILE][64];

    const int bx  = blockIdx.x;
    const int dir = bx >> 7;
    const int b   = (bx >> 4) & 7;
    const int dch = bx & 15;
    const int tid = threadIdx.x;
    const int c    = tid >> 1;
    const int half = tid & 1;
    const int d    = dch*64 + c;
    const int noff = half*8;

    float a[8], h[8];
#pragma unroll
    for (int j=0;j<8;j++){
        a[j] = -expf(A_log[(size_t)d*NSTATE + noff + j]);
        h[j] = 0.f;
    }
    const float a0 = -expf(A_log[(size_t)d*NSTATE]);
    unsigned ok = 1u;
#pragma unroll
    for (int j=0;j<8;j++){
        const float expect = a0*(float)(noff+j+1);
        ok &= (fabsf(a[j] - expect) <= 1e-4f*fabsf(a[j])) ? 1u : 0u;
    }
    ok &= __shfl_xor_sync(0xffffffffu, ok, 1);
    const bool fast = (ok != 0u);
    const float Dv = Dp[d];

    float w[16];
#pragma unroll
    for (int r=0;r<16;r++) w[r] = dtw[(size_t)d*RK + half*16 + r];
    const float bias = dtb[d];

    const size_t cb = (size_t)dir*NT*DI + (size_t)b*LL*DI + (size_t)dch*64;
    const __half* xch = xc_hi + cb;
    const __half* xcl = xc_lo + cb;
    __half* yph = y_hi + cb;
    __half* ypl = y_lo + cb;
    const float* xdp = xdbl + ((size_t)dir*NT + (size_t)b*LL)*64;
    const float* zp  = xz + (size_t)b*LL*(2*DI) + DI + (size_t)dch*64;

    for (int t0=0; t0<LL; t0+=TTILE){
        __syncthreads();
#pragma unroll
        for (int k=0;k<8;k++){
            const int idx = tid + k*128;
            const int row = idx>>6, col = idx&63;
            const int t = t0 + row;
            su [row][col] = __half2float(xch[(size_t)t*DI + col])
                          + __half2float(xcl[(size_t)t*DI + col]);
            sXD[row][col] = xdp[(size_t)t*64 + col];
            const int zt = dir ? (LL-1-t) : t;
            sz [row][col] = zp[(size_t)zt*(2*DI) + col];
        }
        __syncthreads();

        float dtv[TTILE];
#pragma unroll
        for (int i=0;i<TTILE;i++){
            float s0=0.f,s1=0.f,s2=0.f,s3=0.f;
            const float* xr = &sXD[i][half*16];
#pragma unroll
            for (int r=0;r<16;r+=4){
                s0 += xr[r+0]*w[r+0];
                s1 += xr[r+1]*w[r+1];
                s2 += xr[r+2]*w[r+2];
                s3 += xr[r+3]*w[r+3];
            }
            float v = (s0+s1)+(s2+s3);
            v += __shfl_xor_sync(0xffffffffu, v, 1);
            v += bias;
            dtv[i] = (v > 20.f) ? v : __logf(1.f + __expf(v));
        }

        if (fast){
#pragma unroll
            for (int i=0;i<TTILE;i++){
                const float dt  = dtv[i];
                const float u   = su[i][c];
                const float dtu = dt * u;
                const float rr  = __expf(dt * a0);
                const float r2 = rr*rr, r4 = r2*r2;
                const float r3 = r2*rr, r5 = r4*rr, r6 = r4*r2, r7 = r4*r3, r8 = r4*r4;
                const float base = half ? r8 : 1.f;
                const float p[8] = {base*rr, base*r2, base*r3, base*r4,
                                    base*r5, base*r6, base*r7, base*r8};
                float y0=0.f, y1=0.f;
#pragma unroll
                for (int j=0;j<8;j++){
                    h[j] = p[j]*h[j] + dtu * sXD[i][32+noff+j];
                    const float cterm = h[j] * sXD[i][48+noff+j];
                    if (j&1) y1 += cterm; else y0 += cterm;
                }
                float ys = y0 + y1;
                ys += __shfl_xor_sync(0xffffffffu, ys, 1);
                if (half==0){
                    const float y = (u*Dv + ys) * silu_fast(sz[i][c]);
                    __half hv, lv;
                    split_f16(y, hv, lv);
                    yph[(size_t)(t0+i)*DI + c] = hv;
                    ypl[(size_t)(t0+i)*DI + c] = lv;
                }
            }
        } else {
#pragma unroll
            for (int i=0;i<TTILE;i++){
                const float dt  = dtv[i];
                const float u   = su[i][c];
                const float dtu = dt * u;
                float y0=0.f, y1=0.f;
#pragma unroll
                for (int j=0;j<8;j++){
                    const float dA = __expf(dt * a[j]);
                    h[j] = dA*h[j] + dtu * sXD[i][32+noff+j];
                    const float cterm = h[j] * sXD[i][48+noff+j];
                    if (j&1) y1 += cterm; else y0 += cterm;
                }
                float ys = y0 + y1;
                ys += __shfl_xor_sync(0xffffffffu, ys, 1);
                if (half==0){
                    const float y = (u*Dv + ys) * silu_fast(sz[i][c]);
                    __half hv, lv;
                    split_f16(y, hv, lv);
                    yph[(size_t)(t0+i)*DI + c] = hv;
                    ypl[(size_t)(t0+i)*DI + c] = lv;
                }
            }
        }
    }
}

// ---------------------------------------------------------------------------
// Final output: hidden[b,t,:] = o_fwd[b,t,:] + o_bwd[b,L-1-t,:]
// ---------------------------------------------------------------------------
__global__ void __launch_bounds__(256) add_kernel(
    const float* __restrict__ o, float* __restrict__ dst)
{
    const int flat = blockIdx.x*256 + threadIdx.x;
    const int e = flat & (DM-1);
    const int t = (flat >> 9) & (LL-1);
    const int b = flat >> 19;
    const int tok  = b*LL + t;
    const int tokb = b*LL + (LL-1-t);
    dst[flat] = o[(size_t)tok*DM + e] + o[(size_t)(NT + tokb)*DM + e];
}

// ---------------------------------------------------------------------------
// Launch
// ---------------------------------------------------------------------------
extern "C" void kernel_launch(void* const* d_in, const int* in_sizes, int n_in,
                              void* d_out, int out_size)
{
    (void)in_sizes; (void)n_in; (void)out_size;
    const float* x      = (const float*)d_in[0];
    const float* norm_w = (const float*)d_in[1];
    const float* norm_b = (const float*)d_in[2];
    const float* in_w   = (const float*)d_in[3];
    const float* conv_w = (const float*)d_in[4];
    const float* conv_b = (const float*)d_in[5];
    const float* xp_w   = (const float*)d_in[6];
    const float* dtp_w  = (const float*)d_in[7];
    const float* dtp_b  = (const float*)d_in[8];
    const float* A_log  = (const float*)d_in[9];
    const float* Dp     = (const float*)d_in[10];
    const float* out_w  = (const float*)d_in[11];
    float* dout = (float*)d_out;

    float *resid,*xz,*xdbl,*ob;
    __half *hhi,*hlo,*xchi,*xclo,*yhi,*ylo,*w1,*w2,*w4;
    cudaGetSymbolAddress((void**)&resid, g_resid);
    cudaGetSymbolAddress((void**)&xz,    g_xz);
    cudaGetSymbolAddress((void**)&xdbl,  g_xdbl);
    cudaGetSymbolAddress((void**)&ob,    g_o);
    cudaGetSymbolAddress((void**)&hhi,   g_h_hi);
    cudaGetSymbolAddress((void**)&hlo,   g_h_lo);
    cudaGetSymbolAddress((void**)&xchi,  g_xc_hi);
    cudaGetSymbolAddress((void**)&xclo,  g_xc_lo);
    cudaGetSymbolAddress((void**)&yhi,   g_y_hi);
    cudaGetSymbolAddress((void**)&ylo,   g_y_lo);
    cudaGetSymbolAddress((void**)&w1,    g_w1);
    cudaGetSymbolAddress((void**)&w2,    g_w2);
    cudaGetSymbolAddress((void**)&w4,    g_w4);

    constexpr int SMEM_BIG = 3*(2*128*64 + 128*64);   // 73728 (128x128, 3 stages)
    constexpr int SMEM_MED = 3*(2*128*64 + 64*64);    // 61440 (128x64, 3 stages)
    static bool attr_done = false;
    if (!attr_done){
        cudaFuncSetAttribute((const void*)gemm_f16_kernel<128,128>,
                             cudaFuncAttributeMaxDynamicSharedMemorySize, SMEM_BIG);
        cudaFuncSetAttribute((const void*)gemm_f16_kernel<128,64>,
                             cudaFuncAttributeMaxDynamicSharedMemorySize, SMEM_MED);
        attr_done = true;
    }

    // weight conversion (single fp16 plane, all layers)
    {
        const int n1 = DEPTH*2*DI*DM/4, n2 = DEPTH*64*DI/4, n4 = DEPTH*DM*DI/4;
        wcvt_kernel<<<(n1+255)/256,256>>>(in_w,  w1, n1);
        wcvt_kernel<<<(n2+255)/256,256>>>(xp_w,  w2, n2);
        wcvt_kernel<<<(n4+255)/256,256>>>(out_w, w4, n4);
    }

    for (int i=0;i<DEPTH;i++){
        ln_kernel<<<NT,128>>>( (i==0)? x : resid, (i==0)? (const float*)nullptr : ob,
                               resid, norm_w + i*DM, norm_b + i*DM, hhi, hlo );

        // GEMM1: xz[8192,2048] = h @ in_w^T
        gemm_f16_kernel<128,128><<<dim3(2048/128, 8192/128), 128, SMEM_BIG>>>(
            hhi, hlo, DM, w1 + (size_t)i*2*DI*DM, DM, xz, 2*DI);

        conv_kernel<<<(2*NT*DI)/256,256>>>(xz, conv_w + i*DI*4, conv_b + i*DI,
                                           xchi, xclo);

        // GEMM2: xdbl[16384,64] = xc @ xp_w^T
        gemm_f16_kernel<128,64><<<dim3(1, 16384/128), 128, SMEM_MED>>>(
            xchi, xclo, DI, w2 + (size_t)i*64*DI, DI, xdbl, 64);

        scan_kernel<<<256,128>>>(xchi, xclo, xdbl, xz,
                                 A_log + (size_t)i*DI*NSTATE, Dp + i*DI,
                                 dtp_w + (size_t)i*DI*RK, dtp_b + i*DI, yhi, ylo);

        // GEMM4: o[16384,512] = y @ out_w^T
        gemm_f16_kernel<128,128><<<dim3(512/128, 16384/128), 128, SMEM_BIG>>>(
            yhi, ylo, DI, w4 + (size_t)i*DM*DI, DI, ob, DM);
    }
    add_kernel<<<(NT*DM)/256,256>>>(ob, dout);
}

// round 10
// speedup vs baseline: 1.4247x; 1.0504x over previous
#include <cuda_runtime.h>
#include <cuda_fp16.h>
#include <cstdint>
#include <cstddef>

// ---------------------------------------------------------------------------
// Problem constants
// ---------------------------------------------------------------------------
#define BB      8
#define LL      1024
#define DM      512
#define DI      1024
#define NSTATE  16
#define RK      32
#define NT      (BB*LL)          // 8192 tokens
#define DEPTH   4

// ---------------------------------------------------------------------------
// Scratch buffers
// ---------------------------------------------------------------------------
__device__ float  g_resid[NT*DM];
__device__ __half g_h    [NT*DM];        // single fp16 plane (GEMM1 A)
__device__ float  g_xz   [NT*2*DI];
__device__ __half g_xc_hi[2*NT*DI];      // exact hi/lo pair (scan u, GEMM2 A)
__device__ __half g_xc_lo[2*NT*DI];
__device__ float  g_xdbl [2*NT*64];
__device__ __half g_y    [2*NT*DI];      // single fp16 plane (GEMM4 A)
__device__ float  g_o    [2*NT*DM];
// converted weights (single fp16 plane), all layers
__device__ __half g_w1[DEPTH*2*DI*DM];
__device__ __half g_w2[DEPTH*64*DI];
__device__ __half g_w4[DEPTH*DM*DI];

// ---------------------------------------------------------------------------
// Helpers
// ---------------------------------------------------------------------------
__device__ __forceinline__ uint32_t smem_u32(const void* p){
    uint32_t a;
    asm("{ .reg .u64 t; cvta.to.shared.u64 t, %1; cvt.u32.u64 %0, t; }" : "=r"(a) : "l"(p));
    return a;
}
__device__ __forceinline__ float warpReduceSum(float v){
#pragma unroll
    for (int o=16;o>0;o>>=1) v += __shfl_xor_sync(0xffffffffu, v, o);
    return v;
}
__device__ __forceinline__ float silu_fast(float x){
    return x / (1.f + __expf(-x));
}
__device__ __forceinline__ void ldm_x4(uint32_t* r, uint32_t addr){
    asm volatile("ldmatrix.sync.aligned.m8n8.x4.shared.b16 {%0,%1,%2,%3}, [%4];"
        : "=r"(r[0]), "=r"(r[1]), "=r"(r[2]), "=r"(r[3]) : "r"(addr));
}
__device__ __forceinline__ void mma_f16(float* c, const uint32_t* a, const uint32_t* b){
    asm volatile(
        "mma.sync.aligned.m16n8k16.row.col.f32.f16.f16.f32 "
        "{%0,%1,%2,%3}, {%4,%5,%6,%7}, {%8,%9}, {%0,%1,%2,%3};"
        : "+f"(c[0]), "+f"(c[1]), "+f"(c[2]), "+f"(c[3])
        : "r"(a[0]), "r"(a[1]), "r"(a[2]), "r"(a[3]), "r"(b[0]), "r"(b[1]));
}
__device__ __forceinline__ void cp_async16(uint32_t dst, const void* src){
    asm volatile("cp.async.cg.shared.global [%0], [%1], 16;" :: "r"(dst), "l"(src));
}
__device__ __forceinline__ void cp_commit(){
    asm volatile("cp.async.commit_group;");
}
template<int N>
__device__ __forceinline__ void cp_wait(){
    asm volatile("cp.async.wait_group %0;" :: "n"(N));
}
__device__ __forceinline__ void split_f16(float v, __half& hi, __half& lo){
    hi = __float2half_rn(v);
    lo = __float2half_rn(v - __half2float(hi));
}
__device__ __forceinline__ uint32_t pack_h2(__half a, __half b){
    __half2 h = __halves2half2(a, b);
    return *reinterpret_cast<uint32_t*>(&h);
}
// XOR chunk swizzle for 64B rows (4x16B chunks); conflict-free ldmatrix.
__device__ __forceinline__ uint32_t swz(int r, int q){
    return (uint32_t)(r*64 + ((q ^ ((r>>1)&3))<<4));
}

// ---------------------------------------------------------------------------
// Weight conversion: fp32 -> single fp16 plane
// ---------------------------------------------------------------------------
__global__ void __launch_bounds__(256) wcvt_kernel(
    const float* __restrict__ src, __half* __restrict__ dst, int n4)
{
    const int i = blockIdx.x*256 + threadIdx.x;
    if (i >= n4) return;
    float4 v = reinterpret_cast<const float4*>(src)[i];
    uint2 o;
    o.x = pack_h2(__float2half_rn(v.x), __float2half_rn(v.y));
    o.y = pack_h2(__float2half_rn(v.z), __float2half_rn(v.w));
    reinterpret_cast<uint2*>(dst)[i] = o;
}

// ---------------------------------------------------------------------------
// LayerNorm + residual (+ fused bidirectional add); writes h as ONE fp16 plane.
// ---------------------------------------------------------------------------
__global__ void __launch_bounds__(128) ln_kernel(
    const float* __restrict__ src0, const float* __restrict__ o,
    float* __restrict__ resid,
    const float* __restrict__ w, const float* __restrict__ b,
    __half* __restrict__ hout)
{
    __shared__ float sm[8];
    const int row = blockIdx.x, tid = threadIdx.x;
    float4 v = reinterpret_cast<const float4*>(src0 + (size_t)row*DM)[tid];
    if (o){
        const int t    = row & (LL-1);
        const int tokb = (row - t) + (LL-1 - t);
        float4 u1 = reinterpret_cast<const float4*>(o + (size_t)row*DM)[tid];
        float4 u2 = reinterpret_cast<const float4*>(o + (size_t)(NT + tokb)*DM)[tid];
        v.x += u1.x+u2.x; v.y += u1.y+u2.y; v.z += u1.z+u2.z; v.w += u1.w+u2.w;
    }
    reinterpret_cast<float4*>(resid + (size_t)row*DM)[tid] = v;

    float s = v.x+v.y+v.z+v.w;
    s = warpReduceSum(s);
    const int wid = tid>>5, lane = tid&31;
    if (lane==0) sm[wid]=s;
    __syncthreads();
    const float mu = (sm[0]+sm[1]+sm[2]+sm[3]) * (1.f/(float)DM);
    const float dx=v.x-mu, dy=v.y-mu, dz=v.z-mu, dw=v.w-mu;
    float q = dx*dx+dy*dy+dz*dz+dw*dw;
    q = warpReduceSum(q);
    if (lane==0) sm[4+wid]=q;
    __syncthreads();
    const float var = (sm[4]+sm[5]+sm[6]+sm[7]) * (1.f/(float)DM);
    const float rs = rsqrtf(var + 1e-5f);
    const float4 wv = reinterpret_cast<const float4*>(w)[tid];
    const float4 bv = reinterpret_cast<const float4*>(b)[tid];
    float4 ov;
    ov.x = dx*rs*wv.x + bv.x;
    ov.y = dy*rs*wv.y + bv.y;
    ov.z = dz*rs*wv.z + bv.z;
    ov.w = dw*rs*wv.w + bv.w;
    uint2 H;
    H.x = pack_h2(__float2half_rn(ov.x), __float2half_rn(ov.y));
    H.y = pack_h2(__float2half_rn(ov.z), __float2half_rn(ov.w));
    reinterpret_cast<uint2*>(hout + (size_t)row*DM)[tid] = H;
}

// ---------------------------------------------------------------------------
// fp16 MMA GEMM: C = (sum of NA A-planes) @ W^T (W fp16).
// NA=1: single-plane A (1 MMA/slice). NA=2: hi+lo A (2 MMAs/slice).
// 128 threads, 4 warps 2x2, warp tile (BM/2)x(BN/2).
// 3-stage cp.async pipeline, one barrier per chunk, 64B swizzled rows.
// ---------------------------------------------------------------------------
template<int BM,int BN,int NA>
__global__ void __launch_bounds__(128) gemm_f16_kernel(
    const __half* __restrict__ Ahi, const __half* __restrict__ Alo, int lda,
    const __half* __restrict__ W, int K,
    float* __restrict__ C, int ldc)
{
    constexpr int WM  = BM/2;
    constexpr int WN  = BN/2;
    constexpr int MT  = WM/16;
    constexpr int NTL = WN/8;
    constexpr int AHI = 0;
    constexpr int ALO = BM*64;                 // valid only if NA==2
    constexpr int BOF = NA*BM*64;
    constexpr int STAGE = NA*BM*64 + BN*64;

    extern __shared__ __align__(16) char smem[];
    const uint32_t sb = smem_u32(smem);

    const int tid  = threadIdx.x;
    const int wid  = tid>>5, lane = tid&31;
    const int m0   = blockIdx.y*BM, n0 = blockIdx.x*BN;
    const int wm0  = (wid>>1)*WM;
    const int wn0  = (wid&1)*WN;

    float acc[MT][NTL][4];
#pragma unroll
    for (int i=0;i<MT;i++)
#pragma unroll
        for (int j=0;j<NTL;j++)
#pragma unroll
            for (int q=0;q<4;q++) acc[i][j][q]=0.f;

    const int a_row = (lane&7) + ((lane>>3)&1)*8;
    const int aq    = lane>>4;
    const int b_row = (lane&7) + (lane>>4)*8;
    const int bq    = (lane>>3)&1;

    auto issue_stage = [&](int s, int k0){
        const uint32_t base = sb + (uint32_t)(s*STAGE);
#pragma unroll
        for (int u=0; u<BM/32; ++u){
            const int id = tid + u*128;
            const int r = id>>2, q = id&3;
            const size_t go = (size_t)(m0+r)*lda + k0 + q*8;
            cp_async16(base + AHI + swz(r,q), Ahi + go);
            if (NA==2) cp_async16(base + ALO + swz(r,q), Alo + go);
        }
#pragma unroll
        for (int u=0; u<BN/32; ++u){
            const int id = tid + u*128;
            const int r = id>>2, q = id&3;
            cp_async16(base + BOF + swz(r,q), W + (size_t)(n0+r)*K + k0 + q*8);
        }
        cp_commit();
    };

    const int nchunk = K >> 5;
    issue_stage(0, 0);
    issue_stage(1, 32);

    for (int c=0; c<nchunk; ++c){
        if (c+1 < nchunk) cp_wait<1>(); else cp_wait<0>();
        __syncthreads();
        if (c+2 < nchunk) issue_stage((c+2)%3, (c+2)*32);

        const uint32_t sbs = sb + (uint32_t)((c%3)*STAGE);
#pragma unroll
        for (int ks=0; ks<2; ++ks){
            uint32_t ah[MT][4], al[MT][4];
#pragma unroll
            for (int mt=0; mt<MT; ++mt){
                const int row = wm0 + mt*16 + a_row;
                const uint32_t ra = swz(row, ks*2 + aq);
                ldm_x4(ah[mt], sbs + AHI + ra);
                if (NA==2) ldm_x4(al[mt], sbs + ALO + ra);
            }
            uint32_t bh[NTL][2];
#pragma unroll
            for (int tp=0; tp<NTL/2; ++tp){
                const int row = wn0 + tp*16 + b_row;
                const uint32_t rb = swz(row, ks*2 + bq);
                uint32_t t4[4];
                ldm_x4(t4, sbs + BOF + rb);
                bh[tp*2][0]=t4[0]; bh[tp*2][1]=t4[1];
                bh[tp*2+1][0]=t4[2]; bh[tp*2+1][1]=t4[3];
            }
#pragma unroll
            for (int mt=0; mt<MT; ++mt)
#pragma unroll
                for (int nt=0; nt<NTL; ++nt)
                    mma_f16(acc[mt][nt], ah[mt], bh[nt]);
            if (NA==2){
#pragma unroll
                for (int mt=0; mt<MT; ++mt)
#pragma unroll
                    for (int nt=0; nt<NTL; ++nt)
                        mma_f16(acc[mt][nt], al[mt], bh[nt]);
            }
        }
    }

    const int cr = lane>>2;
    const int cc = (lane&3)*2;
#pragma unroll
    for (int mt=0; mt<MT; ++mt){
        const int rbase = m0 + wm0 + mt*16 + cr;
#pragma unroll
        for (int nt=0; nt<NTL; ++nt){
            const int col = n0 + wn0 + nt*8 + cc;
            float2 v0; v0.x = acc[mt][nt][0]; v0.y = acc[mt][nt][1];
            float2 v1; v1.x = acc[mt][nt][2]; v1.y = acc[mt][nt][3];
            *reinterpret_cast<float2*>(C + (size_t)rbase*ldc + col)     = v0;
            *reinterpret_cast<float2*>(C + (size_t)(rbase+8)*ldc + col) = v1;
        }
    }
}

// ---------------------------------------------------------------------------
// Depthwise causal conv (k=4) + bias + silu; writes xc as fp16 hi/lo planes.
// ---------------------------------------------------------------------------
__global__ void __launch_bounds__(256) conv_kernel(
    const float* __restrict__ xz,
    const float* __restrict__ cw, const float* __restrict__ cb,
    __half* __restrict__ xc_hi, __half* __restrict__ xc_lo)
{
    const int flat = blockIdx.x*256 + threadIdx.x;
    const int d   = flat & (DI-1);
    const int t   = (flat >> 10) & (LL-1);
    const int b   = (flat >> 20) & (BB-1);
    const int dir = flat >> 23;

    float acc = cb[d];
    const float w0=cw[d*4+0], w1=cw[d*4+1], w2=cw[d*4+2], w3=cw[d*4+3];
    const float* src = xz + ((size_t)b*LL)*(2*DI) + d;
#pragma unroll
    for (int j=0;j<4;j++){
        const int tt = t - 3 + j;
        if (tt >= 0){
            const int st = dir ? (LL-1-tt) : tt;
            const float wj = (j==0)?w0:(j==1)?w1:(j==2)?w2:w3;
            acc += wj * src[(size_t)st*(2*DI)];
        }
    }
    acc = silu_fast(acc);
    __half hv, lv;
    split_f16(acc, hv, lv);
    const size_t idx = (size_t)dir*NT*DI + ((size_t)(b*LL+t))*DI + d;
    xc_hi[idx] = hv;
    xc_lo[idx] = lv;
}

// ---------------------------------------------------------------------------
// Selective scan, 2 threads per channel (8 states each), fused dt projection.
// Reads u = hi+lo (exact); writes y as ONE fp16 plane.
// ---------------------------------------------------------------------------
#define TTILE 16
__global__ void __launch_bounds__(128) scan_kernel(
    const __half* __restrict__ xc_hi, const __half* __restrict__ xc_lo,
    const float* __restrict__ xdbl, const float* __restrict__ xz,
    const float* __restrict__ A_log,const float* __restrict__ Dp,
    const float* __restrict__ dtw,  const float* __restrict__ dtb,
    __half* __restrict__ yout)
{
    __shared__ float su [TTILE][64];
    __shared__ float sz [TTILE][64];
    __shared__ float sXD[TTILE][64];

    const int bx  = blockIdx.x;
    const int dir = bx >> 7;
    const int b   = (bx >> 4) & 7;
    const int dch = bx & 15;
    const int tid = threadIdx.x;
    const int c    = tid >> 1;
    const int half = tid & 1;
    const int d    = dch*64 + c;
    const int noff = half*8;

    float a[8], h[8];
#pragma unroll
    for (int j=0;j<8;j++){
        a[j] = -expf(A_log[(size_t)d*NSTATE + noff + j]);
        h[j] = 0.f;
    }
    const float a0 = -expf(A_log[(size_t)d*NSTATE]);
    unsigned ok = 1u;
#pragma unroll
    for (int j=0;j<8;j++){
        const float expect = a0*(float)(noff+j+1);
        ok &= (fabsf(a[j] - expect) <= 1e-4f*fabsf(a[j])) ? 1u : 0u;
    }
    ok &= __shfl_xor_sync(0xffffffffu, ok, 1);
    const bool fast = (ok != 0u);
    const float Dv = Dp[d];

    float w[16];
#pragma unroll
    for (int r=0;r<16;r++) w[r] = dtw[(size_t)d*RK + half*16 + r];
    const float bias = dtb[d];

    const size_t cb = (size_t)dir*NT*DI + (size_t)b*LL*DI + (size_t)dch*64;
    const __half* xch = xc_hi + cb;
    const __half* xcl = xc_lo + cb;
    __half* yp = yout + cb;
    const float* xdp = xdbl + ((size_t)dir*NT + (size_t)b*LL)*64;
    const float* zp  = xz + (size_t)b*LL*(2*DI) + DI + (size_t)dch*64;

    for (int t0=0; t0<LL; t0+=TTILE){
        __syncthreads();
#pragma unroll
        for (int k=0;k<8;k++){
            const int idx = tid + k*128;
            const int row = idx>>6, col = idx&63;
            const int t = t0 + row;
            su [row][col] = __half2float(xch[(size_t)t*DI + col])
                          + __half2float(xcl[(size_t)t*DI + col]);
            sXD[row][col] = xdp[(size_t)t*64 + col];
            const int zt = dir ? (LL-1-t) : t;
            sz [row][col] = zp[(size_t)zt*(2*DI) + col];
        }
        __syncthreads();

        float dtv[TTILE];
#pragma unroll
        for (int i=0;i<TTILE;i++){
            float s0=0.f,s1=0.f,s2=0.f,s3=0.f;
            const float* xr = &sXD[i][half*16];
#pragma unroll
            for (int r=0;r<16;r+=4){
                s0 += xr[r+0]*w[r+0];
                s1 += xr[r+1]*w[r+1];
                s2 += xr[r+2]*w[r+2];
                s3 += xr[r+3]*w[r+3];
            }
            float v = (s0+s1)+(s2+s3);
            v += __shfl_xor_sync(0xffffffffu, v, 1);
            v += bias;
            dtv[i] = (v > 20.f) ? v : __logf(1.f + __expf(v));
        }

        if (fast){
#pragma unroll
            for (int i=0;i<TTILE;i++){
                const float dt  = dtv[i];
                const float u   = su[i][c];
                const float dtu = dt * u;
                const float rr  = __expf(dt * a0);
                const float r2 = rr*rr, r4 = r2*r2;
                const float r3 = r2*rr, r5 = r4*rr, r6 = r4*r2, r7 = r4*r3, r8 = r4*r4;
                const float base = half ? r8 : 1.f;
                const float p[8] = {base*rr, base*r2, base*r3, base*r4,
                                    base*r5, base*r6, base*r7, base*r8};
                float y0=0.f, y1=0.f;
#pragma unroll
                for (int j=0;j<8;j++){
                    h[j] = p[j]*h[j] + dtu * sXD[i][32+noff+j];
                    const float cterm = h[j] * sXD[i][48+noff+j];
                    if (j&1) y1 += cterm; else y0 += cterm;
                }
                float ys = y0 + y1;
                ys += __shfl_xor_sync(0xffffffffu, ys, 1);
                if (half==0){
                    const float y = (u*Dv + ys) * silu_fast(sz[i][c]);
                    yp[(size_t)(t0+i)*DI + c] = __float2half_rn(y);
                }
            }
        } else {
#pragma unroll
            for (int i=0;i<TTILE;i++){
                const float dt  = dtv[i];
                const float u   = su[i][c];
                const float dtu = dt * u;
                float y0=0.f, y1=0.f;
#pragma unroll
                for (int j=0;j<8;j++){
                    const float dA = __expf(dt * a[j]);
                    h[j] = dA*h[j] + dtu * sXD[i][32+noff+j];
                    const float cterm = h[j] * sXD[i][48+noff+j];
                    if (j&1) y1 += cterm; else y0 += cterm;
                }
                float ys = y0 + y1;
                ys += __shfl_xor_sync(0xffffffffu, ys, 1);
                if (half==0){
                    const float y = (u*Dv + ys) * silu_fast(sz[i][c]);
                    yp[(size_t)(t0+i)*DI + c] = __float2half_rn(y);
                }
            }
        }
    }
}

// ---------------------------------------------------------------------------
// Final output: hidden[b,t,:] = o_fwd[b,t,:] + o_bwd[b,L-1-t,:]
// ---------------------------------------------------------------------------
__global__ void __launch_bounds__(256) add_kernel(
    const float* __restrict__ o, float* __restrict__ dst)
{
    const int flat = blockIdx.x*256 + threadIdx.x;
    const int e = flat & (DM-1);
    const int t = (flat >> 9) & (LL-1);
    const int b = flat >> 19;
    const int tok  = b*LL + t;
    const int tokb = b*LL + (LL-1-t);
    dst[flat] = o[(size_t)tok*DM + e] + o[(size_t)(NT + tokb)*DM + e];
}

// ---------------------------------------------------------------------------
// Launch
// ---------------------------------------------------------------------------
extern "C" void kernel_launch(void* const* d_in, const int* in_sizes, int n_in,
                              void* d_out, int out_size)
{
    (void)in_sizes; (void)n_in; (void)out_size;
    const float* x      = (const float*)d_in[0];
    const float* norm_w = (const float*)d_in[1];
    const float* norm_b = (const float*)d_in[2];
    const float* in_w   = (const float*)d_in[3];
    const float* conv_w = (const float*)d_in[4];
    const float* conv_b = (const float*)d_in[5];
    const float* xp_w   = (const float*)d_in[6];
    const float* dtp_w  = (const float*)d_in[7];
    const float* dtp_b  = (const float*)d_in[8];
    const float* A_log  = (const float*)d_in[9];
    const float* Dp     = (const float*)d_in[10];
    const float* out_w  = (const float*)d_in[11];
    float* dout = (float*)d_out;

    float *resid,*xz,*xdbl,*ob;
    __half *hbuf,*xchi,*xclo,*yb,*w1,*w2,*w4;
    cudaGetSymbolAddress((void**)&resid, g_resid);
    cudaGetSymbolAddress((void**)&xz,    g_xz);
    cudaGetSymbolAddress((void**)&xdbl,  g_xdbl);
    cudaGetSymbolAddress((void**)&ob,    g_o);
    cudaGetSymbolAddress((void**)&hbuf,  g_h);
    cudaGetSymbolAddress((void**)&xchi,  g_xc_hi);
    cudaGetSymbolAddress((void**)&xclo,  g_xc_lo);
    cudaGetSymbolAddress((void**)&yb,    g_y);
    cudaGetSymbolAddress((void**)&w1,    g_w1);
    cudaGetSymbolAddress((void**)&w2,    g_w2);
    cudaGetSymbolAddress((void**)&w4,    g_w4);

    constexpr int SMEM_BIG = 3*(128*64 + 128*64);     // 49152 (128x128, NA=1)
    constexpr int SMEM_MED = 3*(2*128*64 + 64*64);    // 61440 (128x64, NA=2)
    static bool attr_done = false;
    if (!attr_done){
        cudaFuncSetAttribute((const void*)gemm_f16_kernel<128,128,1>,
                             cudaFuncAttributeMaxDynamicSharedMemorySize, SMEM_BIG);
        cudaFuncSetAttribute((const void*)gemm_f16_kernel<128,64,2>,
                             cudaFuncAttributeMaxDynamicSharedMemorySize, SMEM_MED);
        attr_done = true;
    }

    // weight conversion (single fp16 plane, all layers)
    {
        const int n1 = DEPTH*2*DI*DM/4, n2 = DEPTH*64*DI/4, n4 = DEPTH*DM*DI/4;
        wcvt_kernel<<<(n1+255)/256,256>>>(in_w,  w1, n1);
        wcvt_kernel<<<(n2+255)/256,256>>>(xp_w,  w2, n2);
        wcvt_kernel<<<(n4+255)/256,256>>>(out_w, w4, n4);
    }

    for (int i=0;i<DEPTH;i++){
        ln_kernel<<<NT,128>>>( (i==0)? x : resid, (i==0)? (const float*)nullptr : ob,
                               resid, norm_w + i*DM, norm_b + i*DM, hbuf );

        // GEMM1: xz[8192,2048] = h @ in_w^T   (1-term fp16 A)
        gemm_f16_kernel<128,128,1><<<dim3(2048/128, 8192/128), 128, SMEM_BIG>>>(
            hbuf, hbuf, DM, w1 + (size_t)i*2*DI*DM, DM, xz, 2*DI);

        conv_kernel<<<(2*NT*DI)/256,256>>>(xz, conv_w + i*DI*4, conv_b + i*DI,
                                           xchi, xclo);

        // GEMM2: xdbl[16384,64] = xc @ xp_w^T   (2-term exact A)
        gemm_f16_kernel<128,64,2><<<dim3(1, 16384/128), 128, SMEM_MED>>>(
            xchi, xclo, DI, w2 + (size_t)i*64*DI, DI, xdbl, 64);

        scan_kernel<<<256,128>>>(xchi, xclo, xdbl, xz,
                                 A_log + (size_t)i*DI*NSTATE, Dp + i*DI,
                                 dtp_w + (size_t)i*DI*RK, dtp_b + i*DI, yb);

        // GEMM4: o[16384,512] = y @ out_w^T   (1-term fp16 A)
        gemm_f16_kernel<128,128,1><<<dim3(512/128, 16384/128), 128, SMEM_BIG>>>(
            yb, yb, DI, w4 + (size_t)i*DM*DI, DI, ob, DM);
    }
    add_kernel<<<(NT*DM)/256,256>>>(ob, dout);
}

// round 11
// speedup vs baseline: 1.5827x; 1.1109x over previous
#include <cuda_runtime.h>
#include <cuda_fp16.h>
#include <cstdint>
#include <cstddef>

// ---------------------------------------------------------------------------
// Problem constants
// ---------------------------------------------------------------------------
#define BB      8
#define LL      1024
#define DM      512
#define DI      1024
#define NSTATE  16
#define RK      32
#define NT      (BB*LL)          // 8192 tokens
#define DEPTH   4

// ---------------------------------------------------------------------------
// Scratch buffers
// ---------------------------------------------------------------------------
__device__ float  g_resid[NT*DM];
__device__ __half g_h    [NT*DM];        // fp16 (GEMM1 A)
__device__ __half g_xz   [NT*2*DI];      // fp16 (GEMM1 out; conv + gate input)
__device__ __half g_xc   [2*NT*DI];      // fp16 single plane (scan u, GEMM2 A)
__device__ float  g_xdbl [2*NT*64];
__device__ __half g_y    [2*NT*DI];      // fp16 (GEMM4 A)
__device__ float  g_o    [2*NT*DM];
// converted weights (single fp16 plane), all layers
__device__ __half g_w1[DEPTH*2*DI*DM];
__device__ __half g_w2[DEPTH*64*DI];
__device__ __half g_w4[DEPTH*DM*DI];

// ---------------------------------------------------------------------------
// Helpers
// ---------------------------------------------------------------------------
__device__ __forceinline__ uint32_t smem_u32(const void* p){
    uint32_t a;
    asm("{ .reg .u64 t; cvta.to.shared.u64 t, %1; cvt.u32.u64 %0, t; }" : "=r"(a) : "l"(p));
    return a;
}
__device__ __forceinline__ float warpReduceSum(float v){
#pragma unroll
    for (int o=16;o>0;o>>=1) v += __shfl_xor_sync(0xffffffffu, v, o);
    return v;
}
__device__ __forceinline__ float silu_fast(float x){
    return x / (1.f + __expf(-x));
}
__device__ __forceinline__ void ldm_x4(uint32_t* r, uint32_t addr){
    asm volatile("ldmatrix.sync.aligned.m8n8.x4.shared.b16 {%0,%1,%2,%3}, [%4];"
        : "=r"(r[0]), "=r"(r[1]), "=r"(r[2]), "=r"(r[3]) : "r"(addr));
}
__device__ __forceinline__ void mma_f16(float* c, const uint32_t* a, const uint32_t* b){
    asm volatile(
        "mma.sync.aligned.m16n8k16.row.col.f32.f16.f16.f32 "
        "{%0,%1,%2,%3}, {%4,%5,%6,%7}, {%8,%9}, {%0,%1,%2,%3};"
        : "+f"(c[0]), "+f"(c[1]), "+f"(c[2]), "+f"(c[3])
        : "r"(a[0]), "r"(a[1]), "r"(a[2]), "r"(a[3]), "r"(b[0]), "r"(b[1]));
}
__device__ __forceinline__ void cp_async16(uint32_t dst, const void* src){
    asm volatile("cp.async.cg.shared.global [%0], [%1], 16;" :: "r"(dst), "l"(src));
}
__device__ __forceinline__ void cp_commit(){
    asm volatile("cp.async.commit_group;");
}
template<int N>
__device__ __forceinline__ void cp_wait(){
    asm volatile("cp.async.wait_group %0;" :: "n"(N));
}
__device__ __forceinline__ uint32_t pack_h2(__half a, __half b){
    __half2 h = __halves2half2(a, b);
    return *reinterpret_cast<uint32_t*>(&h);
}
// XOR chunk swizzle for 64B rows (4x16B chunks); conflict-free ldmatrix.
__device__ __forceinline__ uint32_t swz(int r, int q){
    return (uint32_t)(r*64 + ((q ^ ((r>>1)&3))<<4));
}

// ---------------------------------------------------------------------------
// Weight conversion: fp32 -> single fp16 plane
// ---------------------------------------------------------------------------
__global__ void __launch_bounds__(256) wcvt_kernel(
    const float* __restrict__ src, __half* __restrict__ dst, int n4)
{
    const int i = blockIdx.x*256 + threadIdx.x;
    if (i >= n4) return;
    float4 v = reinterpret_cast<const float4*>(src)[i];
    uint2 o;
    o.x = pack_h2(__float2half_rn(v.x), __float2half_rn(v.y));
    o.y = pack_h2(__float2half_rn(v.z), __float2half_rn(v.w));
    reinterpret_cast<uint2*>(dst)[i] = o;
}

// ---------------------------------------------------------------------------
// LayerNorm + residual (+ fused bidirectional add); writes h as fp16 plane.
// ---------------------------------------------------------------------------
__global__ void __launch_bounds__(128) ln_kernel(
    const float* __restrict__ src0, const float* __restrict__ o,
    float* __restrict__ resid,
    const float* __restrict__ w, const float* __restrict__ b,
    __half* __restrict__ hout)
{
    __shared__ float sm[8];
    const int row = blockIdx.x, tid = threadIdx.x;
    float4 v = reinterpret_cast<const float4*>(src0 + (size_t)row*DM)[tid];
    if (o){
        const int t    = row & (LL-1);
        const int tokb = (row - t) + (LL-1 - t);
        float4 u1 = reinterpret_cast<const float4*>(o + (size_t)row*DM)[tid];
        float4 u2 = reinterpret_cast<const float4*>(o + (size_t)(NT + tokb)*DM)[tid];
        v.x += u1.x+u2.x; v.y += u1.y+u2.y; v.z += u1.z+u2.z; v.w += u1.w+u2.w;
    }
    reinterpret_cast<float4*>(resid + (size_t)row*DM)[tid] = v;

    float s = v.x+v.y+v.z+v.w;
    s = warpReduceSum(s);
    const int wid = tid>>5, lane = tid&31;
    if (lane==0) sm[wid]=s;
    __syncthreads();
    const float mu = (sm[0]+sm[1]+sm[2]+sm[3]) * (1.f/(float)DM);
    const float dx=v.x-mu, dy=v.y-mu, dz=v.z-mu, dw=v.w-mu;
    float q = dx*dx+dy*dy+dz*dz+dw*dw;
    q = warpReduceSum(q);
    if (lane==0) sm[4+wid]=q;
    __syncthreads();
    const float var = (sm[4]+sm[5]+sm[6]+sm[7]) * (1.f/(float)DM);
    const float rs = rsqrtf(var + 1e-5f);
    const float4 wv = reinterpret_cast<const float4*>(w)[tid];
    const float4 bv = reinterpret_cast<const float4*>(b)[tid];
    float4 ov;
    ov.x = dx*rs*wv.x + bv.x;
    ov.y = dy*rs*wv.y + bv.y;
    ov.z = dz*rs*wv.z + bv.z;
    ov.w = dw*rs*wv.w + bv.w;
    uint2 H;
    H.x = pack_h2(__float2half_rn(ov.x), __float2half_rn(ov.y));
    H.y = pack_h2(__float2half_rn(ov.z), __float2half_rn(ov.w));
    reinterpret_cast<uint2*>(hout + (size_t)row*DM)[tid] = H;
}

// ---------------------------------------------------------------------------
// fp16 MMA GEMM: C = A @ W^T (A, W fp16; C fp32 or fp16 via OT).
// 128 threads, 4 warps 2x2, warp tile (BM/2)x(BN/2).
// 3-stage cp.async pipeline, one barrier per chunk, 64B swizzled rows.
// ---------------------------------------------------------------------------
template<int BM,int BN,typename OT>
__global__ void __launch_bounds__(128) gemm_f16_kernel(
    const __half* __restrict__ A, int lda,
    const __half* __restrict__ W, int K,
    OT* __restrict__ C, int ldc)
{
    constexpr int WM  = BM/2;
    constexpr int WN  = BN/2;
    constexpr int MT  = WM/16;
    constexpr int NTL = WN/8;
    constexpr int BOF = BM*64;
    constexpr int STAGE = BM*64 + BN*64;

    extern __shared__ __align__(16) char smem[];
    const uint32_t sb = smem_u32(smem);

    const int tid  = threadIdx.x;
    const int wid  = tid>>5, lane = tid&31;
    const int m0   = blockIdx.y*BM, n0 = blockIdx.x*BN;
    const int wm0  = (wid>>1)*WM;
    const int wn0  = (wid&1)*WN;

    float acc[MT][NTL][4];
#pragma unroll
    for (int i=0;i<MT;i++)
#pragma unroll
        for (int j=0;j<NTL;j++)
#pragma unroll
            for (int q=0;q<4;q++) acc[i][j][q]=0.f;

    const int a_row = (lane&7) + ((lane>>3)&1)*8;
    const int aq    = lane>>4;
    const int b_row = (lane&7) + (lane>>4)*8;
    const int bq    = (lane>>3)&1;

    auto issue_stage = [&](int s, int k0){
        const uint32_t base = sb + (uint32_t)(s*STAGE);
#pragma unroll
        for (int u=0; u<BM/32; ++u){
            const int id = tid + u*128;
            const int r = id>>2, q = id&3;
            cp_async16(base + swz(r,q), A + (size_t)(m0+r)*lda + k0 + q*8);
        }
#pragma unroll
        for (int u=0; u<BN/32; ++u){
            const int id = tid + u*128;
            const int r = id>>2, q = id&3;
            cp_async16(base + BOF + swz(r,q), W + (size_t)(n0+r)*K + k0 + q*8);
        }
        cp_commit();
    };

    const int nchunk = K >> 5;
    issue_stage(0, 0);
    issue_stage(1, 32);

    for (int c=0; c<nchunk; ++c){
        if (c+1 < nchunk) cp_wait<1>(); else cp_wait<0>();
        __syncthreads();
        if (c+2 < nchunk) issue_stage((c+2)%3, (c+2)*32);

        const uint32_t sbs = sb + (uint32_t)((c%3)*STAGE);
#pragma unroll
        for (int ks=0; ks<2; ++ks){
            uint32_t ah[MT][4];
#pragma unroll
            for (int mt=0; mt<MT; ++mt){
                const int row = wm0 + mt*16 + a_row;
                ldm_x4(ah[mt], sbs + swz(row, ks*2 + aq));
            }
            uint32_t bh[NTL][2];
#pragma unroll
            for (int tp=0; tp<NTL/2; ++tp){
                const int row = wn0 + tp*16 + b_row;
                uint32_t t4[4];
                ldm_x4(t4, sbs + BOF + swz(row, ks*2 + bq));
                bh[tp*2][0]=t4[0]; bh[tp*2][1]=t4[1];
                bh[tp*2+1][0]=t4[2]; bh[tp*2+1][1]=t4[3];
            }
#pragma unroll
            for (int mt=0; mt<MT; ++mt)
#pragma unroll
                for (int nt=0; nt<NTL; ++nt)
                    mma_f16(acc[mt][nt], ah[mt], bh[nt]);
        }
    }

    const int cr = lane>>2;
    const int cc = (lane&3)*2;
#pragma unroll
    for (int mt=0; mt<MT; ++mt){
        const int rbase = m0 + wm0 + mt*16 + cr;
#pragma unroll
        for (int nt=0; nt<NTL; ++nt){
            const int col = n0 + wn0 + nt*8 + cc;
            if (sizeof(OT) == 2){
                __half* Ch = reinterpret_cast<__half*>(C);
                uint32_t p0 = pack_h2(__float2half_rn(acc[mt][nt][0]),
                                      __float2half_rn(acc[mt][nt][1]));
                uint32_t p1 = pack_h2(__float2half_rn(acc[mt][nt][2]),
                                      __float2half_rn(acc[mt][nt][3]));
                *reinterpret_cast<uint32_t*>(Ch + (size_t)rbase*ldc + col)     = p0;
                *reinterpret_cast<uint32_t*>(Ch + (size_t)(rbase+8)*ldc + col) = p1;
            } else {
                float* Cf = reinterpret_cast<float*>(C);
                float2 v0; v0.x = acc[mt][nt][0]; v0.y = acc[mt][nt][1];
                float2 v1; v1.x = acc[mt][nt][2]; v1.y = acc[mt][nt][3];
                *reinterpret_cast<float2*>(Cf + (size_t)rbase*ldc + col)     = v0;
                *reinterpret_cast<float2*>(Cf + (size_t)(rbase+8)*ldc + col) = v1;
            }
        }
    }
}

// ---------------------------------------------------------------------------
// Depthwise causal conv (k=4) + bias + silu; fp16 in (xz), fp16 out (xc).
// ---------------------------------------------------------------------------
__global__ void __launch_bounds__(256) conv_kernel(
    const __half* __restrict__ xz,
    const float* __restrict__ cw, const float* __restrict__ cb,
    __half* __restrict__ xc)
{
    const int flat = blockIdx.x*256 + threadIdx.x;
    const int d   = flat & (DI-1);
    const int t   = (flat >> 10) & (LL-1);
    const int b   = (flat >> 20) & (BB-1);
    const int dir = flat >> 23;

    float acc = cb[d];
    const float w0=cw[d*4+0], w1=cw[d*4+1], w2=cw[d*4+2], w3=cw[d*4+3];
    const __half* src = xz + ((size_t)b*LL)*(2*DI) + d;
#pragma unroll
    for (int j=0;j<4;j++){
        const int tt = t - 3 + j;
        if (tt >= 0){
            const int st = dir ? (LL-1-tt) : tt;
            const float wj = (j==0)?w0:(j==1)?w1:(j==2)?w2:w3;
            acc += wj * __half2float(src[(size_t)st*(2*DI)]);
        }
    }
    acc = silu_fast(acc);
    xc[(size_t)dir*NT*DI + ((size_t)(b*LL+t))*DI + d] = __float2half_rn(acc);
}

// ---------------------------------------------------------------------------
// Selective scan, 2 threads per channel (8 states each), fused dt projection.
// u from fp16 xc; z gate from fp16 xz; writes y fp16.
// ---------------------------------------------------------------------------
#define TTILE 16
__global__ void __launch_bounds__(128) scan_kernel(
    const __half* __restrict__ xc,
    const float* __restrict__ xdbl, const __half* __restrict__ xz,
    const float* __restrict__ A_log,const float* __restrict__ Dp,
    const float* __restrict__ dtw,  const float* __restrict__ dtb,
    __half* __restrict__ yout)
{
    __shared__ float su [TTILE][64];
    __shared__ float sz [TTILE][64];
    __shared__ float sXD[TTILE][64];

    const int bx  = blockIdx.x;
    const int dir = bx >> 7;
    const int b   = (bx >> 4) & 7;
    const int dch = bx & 15;
    const int tid = threadIdx.x;
    const int c    = tid >> 1;
    const int half = tid & 1;
    const int d    = dch*64 + c;
    const int noff = half*8;

    float a[8], h[8];
#pragma unroll
    for (int j=0;j<8;j++){
        a[j] = -expf(A_log[(size_t)d*NSTATE + noff + j]);
        h[j] = 0.f;
    }
    const float a0 = -expf(A_log[(size_t)d*NSTATE]);
    unsigned ok = 1u;
#pragma unroll
    for (int j=0;j<8;j++){
        const float expect = a0*(float)(noff+j+1);
        ok &= (fabsf(a[j] - expect) <= 1e-4f*fabsf(a[j])) ? 1u : 0u;
    }
    ok &= __shfl_xor_sync(0xffffffffu, ok, 1);
    const bool fast = (ok != 0u);
    const float Dv = Dp[d];

    float w[16];
#pragma unroll
    for (int r=0;r<16;r++) w[r] = dtw[(size_t)d*RK + half*16 + r];
    const float bias = dtb[d];

    const size_t cb = (size_t)dir*NT*DI + (size_t)b*LL*DI + (size_t)dch*64;
    const __half* xcp = xc + cb;
    __half* yp = yout + cb;
    const float* xdp = xdbl + ((size_t)dir*NT + (size_t)b*LL)*64;
    const __half* zp = xz + (size_t)b*LL*(2*DI) + DI + (size_t)dch*64;

    for (int t0=0; t0<LL; t0+=TTILE){
        __syncthreads();
#pragma unroll
        for (int k=0;k<8;k++){
            const int idx = tid + k*128;
            const int row = idx>>6, col = idx&63;
            const int t = t0 + row;
            su [row][col] = __half2float(xcp[(size_t)t*DI + col]);
            sXD[row][col] = xdp[(size_t)t*64 + col];
            const int zt = dir ? (LL-1-t) : t;
            sz [row][col] = __half2float(zp[(size_t)zt*(2*DI) + col]);
        }
        __syncthreads();

        float dtv[TTILE];
#pragma unroll
        for (int i=0;i<TTILE;i++){
            float s0=0.f,s1=0.f,s2=0.f,s3=0.f;
            const float* xr = &sXD[i][half*16];
#pragma unroll
            for (int r=0;r<16;r+=4){
                s0 += xr[r+0]*w[r+0];
                s1 += xr[r+1]*w[r+1];
                s2 += xr[r+2]*w[r+2];
                s3 += xr[r+3]*w[r+3];
            }
            float v = (s0+s1)+(s2+s3);
            v += __shfl_xor_sync(0xffffffffu, v, 1);
            v += bias;
            dtv[i] = (v > 20.f) ? v : __logf(1.f + __expf(v));
        }

        if (fast){
#pragma unroll
            for (int i=0;i<TTILE;i++){
                const float dt  = dtv[i];
                const float u   = su[i][c];
                const float dtu = dt * u;
                const float rr  = __expf(dt * a0);
                const float r2 = rr*rr, r4 = r2*r2;
                const float r3 = r2*rr, r5 = r4*rr, r6 = r4*r2, r7 = r4*r3, r8 = r4*r4;
                const float base = half ? r8 : 1.f;
                const float p[8] = {base*rr, base*r2, base*r3, base*r4,
                                    base*r5, base*r6, base*r7, base*r8};
                float y0=0.f, y1=0.f;
#pragma unroll
                for (int j=0;j<8;j++){
                    h[j] = p[j]*h[j] + dtu * sXD[i][32+noff+j];
                    const float cterm = h[j] * sXD[i][48+noff+j];
                    if (j&1) y1 += cterm; else y0 += cterm;
                }
                float ys = y0 + y1;
                ys += __shfl_xor_sync(0xffffffffu, ys, 1);
                if (half==0){
                    const float y = (u*Dv + ys) * silu_fast(sz[i][c]);
                    yp[(size_t)(t0+i)*DI + c] = __float2half_rn(y);
                }
            }
        } else {
#pragma unroll
            for (int i=0;i<TTILE;i++){
                const float dt  = dtv[i];
                const float u   = su[i][c];
                const float dtu = dt * u;
                float y0=0.f, y1=0.f;
#pragma unroll
                for (int j=0;j<8;j++){
                    const float dA = __expf(dt * a[j]);
                    h[j] = dA*h[j] + dtu * sXD[i][32+noff+j];
                    const float cterm = h[j] * sXD[i][48+noff+j];
                    if (j&1) y1 += cterm; else y0 += cterm;
                }
                float ys = y0 + y1;
                ys += __shfl_xor_sync(0xffffffffu, ys, 1);
                if (half==0){
                    const float y = (u*Dv + ys) * silu_fast(sz[i][c]);
                    yp[(size_t)(t0+i)*DI + c] = __float2half_rn(y);
                }
            }
        }
    }
}

// ---------------------------------------------------------------------------
// Final output: hidden[b,t,:] = o_fwd[b,t,:] + o_bwd[b,L-1-t,:]
// ---------------------------------------------------------------------------
__global__ void __launch_bounds__(256) add_kernel(
    const float* __restrict__ o, float* __restrict__ dst)
{
    const int flat = blockIdx.x*256 + threadIdx.x;
    const int e = flat & (DM-1);
    const int t = (flat >> 9) & (LL-1);
    const int b = flat >> 19;
    const int tok  = b*LL + t;
    const int tokb = b*LL + (LL-1-t);
    dst[flat] = o[(size_t)tok*DM + e] + o[(size_t)(NT + tokb)*DM + e];
}

// ---------------------------------------------------------------------------
// Launch
// ---------------------------------------------------------------------------
extern "C" void kernel_launch(void* const* d_in, const int* in_sizes, int n_in,
                              void* d_out, int out_size)
{
    (void)in_sizes; (void)n_in; (void)out_size;
    const float* x      = (const float*)d_in[0];
    const float* norm_w = (const float*)d_in[1];
    const float* norm_b = (const float*)d_in[2];
    const float* in_w   = (const float*)d_in[3];
    const float* conv_w = (const float*)d_in[4];
    const float* conv_b = (const float*)d_in[5];
    const float* xp_w   = (const float*)d_in[6];
    const float* dtp_w  = (const float*)d_in[7];
    const float* dtp_b  = (const float*)d_in[8];
    const float* A_log  = (const float*)d_in[9];
    const float* Dp     = (const float*)d_in[10];
    const float* out_w  = (const float*)d_in[11];
    float* dout = (float*)d_out;

    float *resid,*xdbl,*ob;
    __half *hbuf,*xzb,*xcb,*yb,*w1,*w2,*w4;
    cudaGetSymbolAddress((void**)&resid, g_resid);
    cudaGetSymbolAddress((void**)&xzb,   g_xz);
    cudaGetSymbolAddress((void**)&xdbl,  g_xdbl);
    cudaGetSymbolAddress((void**)&ob,    g_o);
    cudaGetSymbolAddress((void**)&hbuf,  g_h);
    cudaGetSymbolAddress((void**)&xcb,   g_xc);
    cudaGetSymbolAddress((void**)&yb,    g_y);
    cudaGetSymbolAddress((void**)&w1,    g_w1);
    cudaGetSymbolAddress((void**)&w2,    g_w2);
    cudaGetSymbolAddress((void**)&w4,    g_w4);

    constexpr int SMEM_BIG = 3*(128*64 + 128*64);   // 49152 (128x128)
    constexpr int SMEM_MED = 3*(128*64 + 64*64);    // 36864 (128x64)
    static bool attr_done = false;
    if (!attr_done){
        cudaFuncSetAttribute((const void*)gemm_f16_kernel<128,128,__half>,
                             cudaFuncAttributeMaxDynamicSharedMemorySize, SMEM_BIG);
        cudaFuncSetAttribute((const void*)gemm_f16_kernel<128,128,float>,
                             cudaFuncAttributeMaxDynamicSharedMemorySize, SMEM_BIG);
        cudaFuncSetAttribute((const void*)gemm_f16_kernel<128,64,float>,
                             cudaFuncAttributeMaxDynamicSharedMemorySize, SMEM_MED);
        attr_done = true;
    }

    // weight conversion (single fp16 plane, all layers)
    {
        const int n1 = DEPTH*2*DI*DM/4, n2 = DEPTH*64*DI/4, n4 = DEPTH*DM*DI/4;
        wcvt_kernel<<<(n1+255)/256,256>>>(in_w,  w1, n1);
        wcvt_kernel<<<(n2+255)/256,256>>>(xp_w,  w2, n2);
        wcvt_kernel<<<(n4+255)/256,256>>>(out_w, w4, n4);
    }

    for (int i=0;i<DEPTH;i++){
        ln_kernel<<<NT,128>>>( (i==0)? x : resid, (i==0)? (const float*)nullptr : ob,
                               resid, norm_w + i*DM, norm_b + i*DM, hbuf );

        // GEMM1: xz[8192,2048] = h @ in_w^T   (fp16 out)
        gemm_f16_kernel<128,128,__half><<<dim3(2048/128, 8192/128), 128, SMEM_BIG>>>(
            hbuf, DM, w1 + (size_t)i*2*DI*DM, DM, xzb, 2*DI);

        conv_kernel<<<(2*NT*DI)/256,256>>>(xzb, conv_w + i*DI*4, conv_b + i*DI, xcb);

        // GEMM2: xdbl[16384,64] = xc @ xp_w^T   (fp32 out)
        gemm_f16_kernel<128,64,float><<<dim3(1, 16384/128), 128, SMEM_MED>>>(
            xcb, DI, w2 + (size_t)i*64*DI, DI, xdbl, 64);

        scan_kernel<<<256,128>>>(xcb, xdbl, xzb,
                                 A_log + (size_t)i*DI*NSTATE, Dp + i*DI,
                                 dtp_w + (size_t)i*DI*RK, dtp_b + i*DI, yb);

        // GEMM4: o[16384,512] = y @ out_w^T   (fp32 out)
        gemm_f16_kernel<128,128,float><<<dim3(512/128, 16384/128), 128, SMEM_BIG>>>(
            yb, DI, w4 + (size_t)i*DM*DI, DI, ob, DM);
    }
    add_kernel<<<(NT*DM)/256,256>>>(ob, dout);
}

// round 12
// speedup vs baseline: 1.6488x; 1.0418x over previous
#include <cuda_runtime.h>
#include <cuda_fp16.h>
#include <cstdint>
#include <cstddef>

// ---------------------------------------------------------------------------
// Problem constants
// ---------------------------------------------------------------------------
#define BB      8
#define LL      1024
#define DM      512
#define DI      1024
#define NSTATE  16
#define RK      32
#define NT      (BB*LL)          // 8192 tokens
#define DEPTH   4

// ---------------------------------------------------------------------------
// Scratch buffers
// ---------------------------------------------------------------------------
__device__ float  g_resid[NT*DM];
__device__ __half g_h    [NT*DM];        // fp16 (GEMM1 A)
__device__ __half g_xz   [NT*2*DI];      // fp16 (GEMM1 out; conv + gate input)
__device__ __half g_xc   [2*NT*DI];      // fp16 (scan u, GEMM2 A)
__device__ float  g_xdbl [2*NT*64];
__device__ __half g_y    [2*NT*DI];      // fp16 (GEMM4 A)
__device__ float  g_o    [2*NT*DM];
// converted weights (single fp16 plane), all layers
__device__ __half g_w1[DEPTH*2*DI*DM];
__device__ __half g_w2[DEPTH*64*DI];
__device__ __half g_w4[DEPTH*DM*DI];

// ---------------------------------------------------------------------------
// Helpers
// ---------------------------------------------------------------------------
__device__ __forceinline__ uint32_t smem_u32(const void* p){
    uint32_t a;
    asm("{ .reg .u64 t; cvta.to.shared.u64 t, %1; cvt.u32.u64 %0, t; }" : "=r"(a) : "l"(p));
    return a;
}
__device__ __forceinline__ float warpReduceSum(float v){
#pragma unroll
    for (int o=16;o>0;o>>=1) v += __shfl_xor_sync(0xffffffffu, v, o);
    return v;
}
__device__ __forceinline__ float silu_fast(float x){
    return x / (1.f + __expf(-x));
}
__device__ __forceinline__ void ldm_x4(uint32_t* r, uint32_t addr){
    asm volatile("ldmatrix.sync.aligned.m8n8.x4.shared.b16 {%0,%1,%2,%3}, [%4];"
        : "=r"(r[0]), "=r"(r[1]), "=r"(r[2]), "=r"(r[3]) : "r"(addr));
}
__device__ __forceinline__ void mma_f16(float* c, const uint32_t* a, const uint32_t* b){
    asm volatile(
        "mma.sync.aligned.m16n8k16.row.col.f32.f16.f16.f32 "
        "{%0,%1,%2,%3}, {%4,%5,%6,%7}, {%8,%9}, {%0,%1,%2,%3};"
        : "+f"(c[0]), "+f"(c[1]), "+f"(c[2]), "+f"(c[3])
        : "r"(a[0]), "r"(a[1]), "r"(a[2]), "r"(a[3]), "r"(b[0]), "r"(b[1]));
}
__device__ __forceinline__ void cp_async16(uint32_t dst, const void* src){
    asm volatile("cp.async.cg.shared.global [%0], [%1], 16;" :: "r"(dst), "l"(src));
}
__device__ __forceinline__ void cp_commit(){
    asm volatile("cp.async.commit_group;");
}
template<int N>
__device__ __forceinline__ void cp_wait(){
    asm volatile("cp.async.wait_group %0;" :: "n"(N));
}
__device__ __forceinline__ uint32_t pack_h2(__half a, __half b){
    __half2 h = __halves2half2(a, b);
    return *reinterpret_cast<uint32_t*>(&h);
}
// XOR chunk swizzle for 64B rows (4x16B chunks); conflict-free ldmatrix.
__device__ __forceinline__ uint32_t swz(int r, int q){
    return (uint32_t)(r*64 + ((q ^ ((r>>1)&3))<<4));
}

// ---------------------------------------------------------------------------
// Weight conversion: fp32 -> single fp16 plane
// ---------------------------------------------------------------------------
__global__ void __launch_bounds__(256) wcvt_kernel(
    const float* __restrict__ src, __half* __restrict__ dst, int n4)
{
    const int i = blockIdx.x*256 + threadIdx.x;
    if (i >= n4) return;
    float4 v = reinterpret_cast<const float4*>(src)[i];
    uint2 o;
    o.x = pack_h2(__float2half_rn(v.x), __float2half_rn(v.y));
    o.y = pack_h2(__float2half_rn(v.z), __float2half_rn(v.w));
    reinterpret_cast<uint2*>(dst)[i] = o;
}

// ---------------------------------------------------------------------------
// LayerNorm + residual (+ fused bidirectional add); writes h as fp16 plane.
// ---------------------------------------------------------------------------
__global__ void __launch_bounds__(128) ln_kernel(
    const float* __restrict__ src0, const float* __restrict__ o,
    float* __restrict__ resid,
    const float* __restrict__ w, const float* __restrict__ b,
    __half* __restrict__ hout)
{
    __shared__ float sm[8];
    const int row = blockIdx.x, tid = threadIdx.x;
    float4 v = reinterpret_cast<const float4*>(src0 + (size_t)row*DM)[tid];
    if (o){
        const int t    = row & (LL-1);
        const int tokb = (row - t) + (LL-1 - t);
        float4 u1 = reinterpret_cast<const float4*>(o + (size_t)row*DM)[tid];
        float4 u2 = reinterpret_cast<const float4*>(o + (size_t)(NT + tokb)*DM)[tid];
        v.x += u1.x+u2.x; v.y += u1.y+u2.y; v.z += u1.z+u2.z; v.w += u1.w+u2.w;
    }
    reinterpret_cast<float4*>(resid + (size_t)row*DM)[tid] = v;

    float s = v.x+v.y+v.z+v.w;
    s = warpReduceSum(s);
    const int wid = tid>>5, lane = tid&31;
    if (lane==0) sm[wid]=s;
    __syncthreads();
    const float mu = (sm[0]+sm[1]+sm[2]+sm[3]) * (1.f/(float)DM);
    const float dx=v.x-mu, dy=v.y-mu, dz=v.z-mu, dw=v.w-mu;
    float q = dx*dx+dy*dy+dz*dz+dw*dw;
    q = warpReduceSum(q);
    if (lane==0) sm[4+wid]=q;
    __syncthreads();
    const float var = (sm[4]+sm[5]+sm[6]+sm[7]) * (1.f/(float)DM);
    const float rs = rsqrtf(var + 1e-5f);
    const float4 wv = reinterpret_cast<const float4*>(w)[tid];
    const float4 bv = reinterpret_cast<const float4*>(b)[tid];
    float4 ov;
    ov.x = dx*rs*wv.x + bv.x;
    ov.y = dy*rs*wv.y + bv.y;
    ov.z = dz*rs*wv.z + bv.z;
    ov.w = dw*rs*wv.w + bv.w;
    uint2 H;
    H.x = pack_h2(__float2half_rn(ov.x), __float2half_rn(ov.y));
    H.y = pack_h2(__float2half_rn(ov.z), __float2half_rn(ov.w));
    reinterpret_cast<uint2*>(hout + (size_t)row*DM)[tid] = H;
}

// ---------------------------------------------------------------------------
// fp16 MMA GEMM: C = A @ W^T (A, W fp16; C fp32 or fp16 via OT).
// 128 threads, 4 warps 2x2, warp tile (BM/2)x(BN/2).
// 3-stage cp.async pipeline, one barrier per chunk, 64B swizzled rows.
// ---------------------------------------------------------------------------
template<int BM,int BN,typename OT>
__global__ void __launch_bounds__(128) gemm_f16_kernel(
    const __half* __restrict__ A, int lda,
    const __half* __restrict__ W, int K,
    OT* __restrict__ C, int ldc)
{
    constexpr int WM  = BM/2;
    constexpr int WN  = BN/2;
    constexpr int MT  = WM/16;
    constexpr int NTL = WN/8;
    constexpr int BOF = BM*64;
    constexpr int STAGE = BM*64 + BN*64;

    extern __shared__ __align__(16) char smem[];
    const uint32_t sb = smem_u32(smem);

    const int tid  = threadIdx.x;
    const int wid  = tid>>5, lane = tid&31;
    const int m0   = blockIdx.y*BM, n0 = blockIdx.x*BN;
    const int wm0  = (wid>>1)*WM;
    const int wn0  = (wid&1)*WN;

    float acc[MT][NTL][4];
#pragma unroll
    for (int i=0;i<MT;i++)
#pragma unroll
        for (int j=0;j<NTL;j++)
#pragma unroll
            for (int q=0;q<4;q++) acc[i][j][q]=0.f;

    const int a_row = (lane&7) + ((lane>>3)&1)*8;
    const int aq    = lane>>4;
    const int b_row = (lane&7) + (lane>>4)*8;
    const int bq    = (lane>>3)&1;

    auto issue_stage = [&](int s, int k0){
        const uint32_t base = sb + (uint32_t)(s*STAGE);
#pragma unroll
        for (int u=0; u<BM/32; ++u){
            const int id = tid + u*128;
            const int r = id>>2, q = id&3;
            cp_async16(base + swz(r,q), A + (size_t)(m0+r)*lda + k0 + q*8);
        }
#pragma unroll
        for (int u=0; u<BN/32; ++u){
            const int id = tid + u*128;
            const int r = id>>2, q = id&3;
            cp_async16(base + BOF + swz(r,q), W + (size_t)(n0+r)*K + k0 + q*8);
        }
        cp_commit();
    };

    const int nchunk = K >> 5;
    issue_stage(0, 0);
    issue_stage(1, 32);

    for (int c=0; c<nchunk; ++c){
        if (c+1 < nchunk) cp_wait<1>(); else cp_wait<0>();
        __syncthreads();
        if (c+2 < nchunk) issue_stage((c+2)%3, (c+2)*32);

        const uint32_t sbs = sb + (uint32_t)((c%3)*STAGE);
#pragma unroll
        for (int ks=0; ks<2; ++ks){
            uint32_t ah[MT][4];
#pragma unroll
            for (int mt=0; mt<MT; ++mt){
                const int row = wm0 + mt*16 + a_row;
                ldm_x4(ah[mt], sbs + swz(row, ks*2 + aq));
            }
            uint32_t bh[NTL][2];
#pragma unroll
            for (int tp=0; tp<NTL/2; ++tp){
                const int row = wn0 + tp*16 + b_row;
                uint32_t t4[4];
                ldm_x4(t4, sbs + BOF + swz(row, ks*2 + bq));
                bh[tp*2][0]=t4[0]; bh[tp*2][1]=t4[1];
                bh[tp*2+1][0]=t4[2]; bh[tp*2+1][1]=t4[3];
            }
#pragma unroll
            for (int mt=0; mt<MT; ++mt)
#pragma unroll
                for (int nt=0; nt<NTL; ++nt)
                    mma_f16(acc[mt][nt], ah[mt], bh[nt]);
        }
    }

    const int cr = lane>>2;
    const int cc = (lane&3)*2;
#pragma unroll
    for (int mt=0; mt<MT; ++mt){
        const int rbase = m0 + wm0 + mt*16 + cr;
#pragma unroll
        for (int nt=0; nt<NTL; ++nt){
            const int col = n0 + wn0 + nt*8 + cc;
            if (sizeof(OT) == 2){
                __half* Ch = reinterpret_cast<__half*>(C);
                uint32_t p0 = pack_h2(__float2half_rn(acc[mt][nt][0]),
                                      __float2half_rn(acc[mt][nt][1]));
                uint32_t p1 = pack_h2(__float2half_rn(acc[mt][nt][2]),
                                      __float2half_rn(acc[mt][nt][3]));
                *reinterpret_cast<uint32_t*>(Ch + (size_t)rbase*ldc + col)     = p0;
                *reinterpret_cast<uint32_t*>(Ch + (size_t)(rbase+8)*ldc + col) = p1;
            } else {
                float* Cf = reinterpret_cast<float*>(C);
                float2 v0; v0.x = acc[mt][nt][0]; v0.y = acc[mt][nt][1];
                float2 v1; v1.x = acc[mt][nt][2]; v1.y = acc[mt][nt][3];
                *reinterpret_cast<float2*>(Cf + (size_t)rbase*ldc + col)     = v0;
                *reinterpret_cast<float2*>(Cf + (size_t)(rbase+8)*ldc + col) = v1;
            }
        }
    }
}

// ---------------------------------------------------------------------------
// Depthwise causal conv (k=4) + bias + silu; half2 (2 channels per thread).
// ---------------------------------------------------------------------------
__global__ void __launch_bounds__(256) conv_kernel(
    const __half2* __restrict__ xz2,
    const float* __restrict__ cw, const float* __restrict__ cb,
    __half2* __restrict__ xc2)
{
    const int flat = blockIdx.x*256 + threadIdx.x;   // < 2*NT*DI/2
    const int d2  = flat & (DI/2 - 1);               // half2 index (512/row)
    const int t   = (flat >> 9) & (LL-1);
    const int b   = (flat >> 19) & (BB-1);
    const int dir = flat >> 22;
    const int d   = d2*2;

    const float4 w0 = *reinterpret_cast<const float4*>(cw + d*4);
    const float4 w1 = *reinterpret_cast<const float4*>(cw + d*4 + 4);
    float accx = cb[d], accy = cb[d+1];

    const __half2* src = xz2 + (size_t)b*LL*DI + d2;   // row stride DI half2s
#pragma unroll
    for (int j=0;j<4;j++){
        const int tt = t - 3 + j;
        if (tt >= 0){
            const int st = dir ? (LL-1-tt) : tt;
            const float2 v = __half22float2(src[(size_t)st*DI]);
            const float wx = (j==0)?w0.x:(j==1)?w0.y:(j==2)?w0.z:w0.w;
            const float wy = (j==0)?w1.x:(j==1)?w1.y:(j==2)?w1.z:w1.w;
            accx += wx * v.x;
            accy += wy * v.y;
        }
    }
    accx = silu_fast(accx);
    accy = silu_fast(accy);
    xc2[(size_t)dir*NT*(DI/2) + ((size_t)(b*LL+t))*(DI/2) + d2] =
        __floats2half2_rn(accx, accy);
}

// ---------------------------------------------------------------------------
// Selective scan, 2 threads per channel (8 states each), fused dt projection.
// All sXD reads vectorized to LDS.128 (4x fewer LSU instructions).
// ---------------------------------------------------------------------------
#define TTILE 16
__global__ void __launch_bounds__(128) scan_kernel(
    const __half* __restrict__ xc,
    const float* __restrict__ xdbl, const __half* __restrict__ xz,
    const float* __restrict__ A_log,const float* __restrict__ Dp,
    const float* __restrict__ dtw,  const float* __restrict__ dtb,
    __half* __restrict__ yout)
{
    __shared__ float su [TTILE][64];
    __shared__ float sz [TTILE][64];
    __shared__ alignas(16) float sXD[TTILE][64];

    const int bx  = blockIdx.x;
    const int dir = bx >> 7;
    const int b   = (bx >> 4) & 7;
    const int dch = bx & 15;
    const int tid = threadIdx.x;
    const int c    = tid >> 1;
    const int half = tid & 1;
    const int d    = dch*64 + c;
    const int noff = half*8;

    float a[8], h[8];
#pragma unroll
    for (int j=0;j<8;j++){
        a[j] = -expf(A_log[(size_t)d*NSTATE + noff + j]);
        h[j] = 0.f;
    }
    const float a0 = -expf(A_log[(size_t)d*NSTATE]);
    unsigned ok = 1u;
#pragma unroll
    for (int j=0;j<8;j++){
        const float expect = a0*(float)(noff+j+1);
        ok &= (fabsf(a[j] - expect) <= 1e-4f*fabsf(a[j])) ? 1u : 0u;
    }
    ok &= __shfl_xor_sync(0xffffffffu, ok, 1);
    const bool fast = (ok != 0u);
    const float Dv = Dp[d];

    float w[16];
#pragma unroll
    for (int r=0;r<16;r++) w[r] = dtw[(size_t)d*RK + half*16 + r];
    const float bias = dtb[d];

    const size_t cb = (size_t)dir*NT*DI + (size_t)b*LL*DI + (size_t)dch*64;
    const __half* xcp = xc + cb;
    __half* yp = yout + cb;
    const float* xdp = xdbl + ((size_t)dir*NT + (size_t)b*LL)*64;
    const __half* zp = xz + (size_t)b*LL*(2*DI) + DI + (size_t)dch*64;

    for (int t0=0; t0<LL; t0+=TTILE){
        __syncthreads();
#pragma unroll
        for (int k=0;k<8;k++){
            const int idx = tid + k*128;
            const int row = idx>>6, col = idx&63;
            const int t = t0 + row;
            su [row][col] = __half2float(xcp[(size_t)t*DI + col]);
            sXD[row][col] = xdp[(size_t)t*64 + col];
            const int zt = dir ? (LL-1-t) : t;
            sz [row][col] = __half2float(zp[(size_t)zt*(2*DI) + col]);
        }
        __syncthreads();

        float dtv[TTILE];
#pragma unroll
        for (int i=0;i<TTILE;i++){
            const float4* xr4 = reinterpret_cast<const float4*>(&sXD[i][half*16]);
            const float4 x0 = xr4[0], x1 = xr4[1], x2 = xr4[2], x3 = xr4[3];
            float s0 = x0.x*w[0]  + x1.x*w[4]  + x2.x*w[8]  + x3.x*w[12];
            float s1 = x0.y*w[1]  + x1.y*w[5]  + x2.y*w[9]  + x3.y*w[13];
            float s2 = x0.z*w[2]  + x1.z*w[6]  + x2.z*w[10] + x3.z*w[14];
            float s3 = x0.w*w[3]  + x1.w*w[7]  + x2.w*w[11] + x3.w*w[15];
            float v = (s0+s1)+(s2+s3);
            v += __shfl_xor_sync(0xffffffffu, v, 1);
            v += bias;
            dtv[i] = (v > 20.f) ? v : __logf(1.f + __expf(v));
        }

        if (fast){
#pragma unroll
            for (int i=0;i<TTILE;i++){
                const float dt  = dtv[i];
                const float u   = su[i][c];
                const float dtu = dt * u;
                const float4 B0 = *reinterpret_cast<const float4*>(&sXD[i][32+noff]);
                const float4 B1 = *reinterpret_cast<const float4*>(&sXD[i][36+noff]);
                const float4 C0 = *reinterpret_cast<const float4*>(&sXD[i][48+noff]);
                const float4 C1 = *reinterpret_cast<const float4*>(&sXD[i][52+noff]);
                const float Bv[8] = {B0.x,B0.y,B0.z,B0.w,B1.x,B1.y,B1.z,B1.w};
                const float Cv[8] = {C0.x,C0.y,C0.z,C0.w,C1.x,C1.y,C1.z,C1.w};
                const float rr  = __expf(dt * a0);
                const float r2 = rr*rr, r4 = r2*r2;
                const float r3 = r2*rr, r5 = r4*rr, r6 = r4*r2, r7 = r4*r3, r8 = r4*r4;
                const float base = half ? r8 : 1.f;
                const float p[8] = {base*rr, base*r2, base*r3, base*r4,
                                    base*r5, base*r6, base*r7, base*r8};
                float y0=0.f, y1=0.f;
#pragma unroll
                for (int j=0;j<8;j++){
                    h[j] = p[j]*h[j] + dtu * Bv[j];
                    const float cterm = h[j] * Cv[j];
                    if (j&1) y1 += cterm; else y0 += cterm;
                }
                float ys = y0 + y1;
                ys += __shfl_xor_sync(0xffffffffu, ys, 1);
                if (half==0){
                    const float y = (u*Dv + ys) * silu_fast(sz[i][c]);
                    yp[(size_t)(t0+i)*DI + c] = __float2half_rn(y);
                }
            }
        } else {
#pragma unroll
            for (int i=0;i<TTILE;i++){
                const float dt  = dtv[i];
                const float u   = su[i][c];
                const float dtu = dt * u;
                const float4 B0 = *reinterpret_cast<const float4*>(&sXD[i][32+noff]);
                const float4 B1 = *reinterpret_cast<const float4*>(&sXD[i][36+noff]);
                const float4 C0 = *reinterpret_cast<const float4*>(&sXD[i][48+noff]);
                const float4 C1 = *reinterpret_cast<const float4*>(&sXD[i][52+noff]);
                const float Bv[8] = {B0.x,B0.y,B0.z,B0.w,B1.x,B1.y,B1.z,B1.w};
                const float Cv[8] = {C0.x,C0.y,C0.z,C0.w,C1.x,C1.y,C1.z,C1.w};
                float y0=0.f, y1=0.f;
#pragma unroll
                for (int j=0;j<8;j++){
                    const float dA = __expf(dt * a[j]);
                    h[j] = dA*h[j] + dtu * Bv[j];
                    const float cterm = h[j] * Cv[j];
                    if (j&1) y1 += cterm; else y0 += cterm;
                }
                float ys = y0 + y1;
                ys += __shfl_xor_sync(0xffffffffu, ys, 1);
                if (half==0){
                    const float y = (u*Dv + ys) * silu_fast(sz[i][c]);
                    yp[(size_t)(t0+i)*DI + c] = __float2half_rn(y);
                }
            }
        }
    }
}

// ---------------------------------------------------------------------------
// Final output: hidden[b,t,:] = o_fwd[b,t,:] + o_bwd[b,L-1-t,:]
// ---------------------------------------------------------------------------
__global__ void __launch_bounds__(256) add_kernel(
    const float* __restrict__ o, float* __restrict__ dst)
{
    const int flat = blockIdx.x*256 + threadIdx.x;
    const int e = flat & (DM-1);
    const int t = (flat >> 9) & (LL-1);
    const int b = flat >> 19;
    const int tok  = b*LL + t;
    const int tokb = b*LL + (LL-1-t);
    dst[flat] = o[(size_t)tok*DM + e] + o[(size_t)(NT + tokb)*DM + e];
}

// ---------------------------------------------------------------------------
// Launch
// ---------------------------------------------------------------------------
extern "C" void kernel_launch(void* const* d_in, const int* in_sizes, int n_in,
                              void* d_out, int out_size)
{
    (void)in_sizes; (void)n_in; (void)out_size;
    const float* x      = (const float*)d_in[0];
    const float* norm_w = (const float*)d_in[1];
    const float* norm_b = (const float*)d_in[2];
    const float* in_w   = (const float*)d_in[3];
    const float* conv_w = (const float*)d_in[4];
    const float* conv_b = (const float*)d_in[5];
    const float* xp_w   = (const float*)d_in[6];
    const float* dtp_w  = (const float*)d_in[7];
    const float* dtp_b  = (const float*)d_in[8];
    const float* A_log  = (const float*)d_in[9];
    const float* Dp     = (const float*)d_in[10];
    const float* out_w  = (const float*)d_in[11];
    float* dout = (float*)d_out;

    float *resid,*xdbl,*ob;
    __half *hbuf,*xzb,*xcb,*yb,*w1,*w2,*w4;
    cudaGetSymbolAddress((void**)&resid, g_resid);
    cudaGetSymbolAddress((void**)&xzb,   g_xz);
    cudaGetSymbolAddress((void**)&xdbl,  g_xdbl);
    cudaGetSymbolAddress((void**)&ob,    g_o);
    cudaGetSymbolAddress((void**)&hbuf,  g_h);
    cudaGetSymbolAddress((void**)&xcb,   g_xc);
    cudaGetSymbolAddress((void**)&yb,    g_y);
    cudaGetSymbolAddress((void**)&w1,    g_w1);
    cudaGetSymbolAddress((void**)&w2,    g_w2);
    cudaGetSymbolAddress((void**)&w4,    g_w4);

    constexpr int SMEM_BIG = 3*(128*64 + 128*64);   // 49152 (128x128)
    constexpr int SMEM_SML = 3*(64*64 + 64*64);     // 24576 (64x64)
    static bool attr_done = false;
    if (!attr_done){
        cudaFuncSetAttribute((const void*)gemm_f16_kernel<128,128,__half>,
                             cudaFuncAttributeMaxDynamicSharedMemorySize, SMEM_BIG);
        cudaFuncSetAttribute((const void*)gemm_f16_kernel<128,128,float>,
                             cudaFuncAttributeMaxDynamicSharedMemorySize, SMEM_BIG);
        cudaFuncSetAttribute((const void*)gemm_f16_kernel<64,64,float>,
                             cudaFuncAttributeMaxDynamicSharedMemorySize, SMEM_SML);
        attr_done = true;
    }

    // weight conversion (single fp16 plane, all layers)
    {
        const int n1 = DEPTH*2*DI*DM/4, n2 = DEPTH*64*DI/4, n4 = DEPTH*DM*DI/4;
        wcvt_kernel<<<(n1+255)/256,256>>>(in_w,  w1, n1);
        wcvt_kernel<<<(n2+255)/256,256>>>(xp_w,  w2, n2);
        wcvt_kernel<<<(n4+255)/256,256>>>(out_w, w4, n4);
    }

    for (int i=0;i<DEPTH;i++){
        ln_kernel<<<NT,128>>>( (i==0)? x : resid, (i==0)? (const float*)nullptr : ob,
                               resid, norm_w + i*DM, norm_b + i*DM, hbuf );

        // GEMM1: xz[8192,2048] = h @ in_w^T   (fp16 out)
        gemm_f16_kernel<128,128,__half><<<dim3(2048/128, 8192/128), 128, SMEM_BIG>>>(
            hbuf, DM, w1 + (size_t)i*2*DI*DM, DM, xzb, 2*DI);

        conv_kernel<<<(2*NT*DI/2)/256,256>>>(
            reinterpret_cast<const __half2*>(xzb), conv_w + i*DI*4, conv_b + i*DI,
            reinterpret_cast<__half2*>(xcb));

        // GEMM2: xdbl[16384,64] = xc @ xp_w^T   (fp32 out)
        gemm_f16_kernel<64,64,float><<<dim3(1, 16384/64), 128, SMEM_SML>>>(
            xcb, DI, w2 + (size_t)i*64*DI, DI, xdbl, 64);

        scan_kernel<<<256,128>>>(xcb, xdbl, xzb,
                                 A_log + (size_t)i*DI*NSTATE, Dp + i*DI,
                                 dtp_w + (size_t)i*DI*RK, dtp_b + i*DI, yb);

        // GEMM4: o[16384,512] = y @ out_w^T   (fp32 out)
        gemm_f16_kernel<128,128,float><<<dim3(512/128, 16384/128), 128, SMEM_BIG>>>(
            yb, DI, w4 + (size_t)i*DM*DI, DI, ob, DM);
    }
    add_kernel<<<(NT*DM)/256,256>>>(ob, dout);
}